// round 3
// baseline (speedup 1.0000x reference)
#include <cuda_runtime.h>
#include <math.h>

#define BB 2
#define LL 2048
#define DD 1024
#define HH 16
#define DH 64
#define NEGV -10000.0f

// Scratch buffers (allocation-free rule: __device__ globals)
__device__ float g_Q[BB * LL * DD];
__device__ float g_K[BB * LL * DD];
__device__ float g_V[BB * LL * DD];
__device__ float g_Y[BB * LL * DD];

// ---------------------------------------------------------------------------
// GEMM: C[M,N] = A[M,K] @ W[N,K]^T + bias[N]
// Tiles: 128x128x16, 256 threads, 8x8 per thread.
// ---------------------------------------------------------------------------
#define GBM 128
#define GBN 128
#define GBK 16

__global__ __launch_bounds__(256) void gemm_bias(
    const float* __restrict__ A, const float* __restrict__ W,
    const float* __restrict__ bias, float* __restrict__ C,
    int M, int N, int K)
{
    __shared__ float As[GBK][GBM];
    __shared__ float Ws[GBK][GBN];

    const int tid = threadIdx.x;
    const int tx = tid & 15;
    const int ty = tid >> 4;
    const int rowBase = blockIdx.y * GBM;
    const int colBase = blockIdx.x * GBN;

    float acc[8][8];
#pragma unroll
    for (int i = 0; i < 8; i++)
#pragma unroll
        for (int j = 0; j < 8; j++) acc[i][j] = 0.0f;

    for (int k0 = 0; k0 < K; k0 += GBK) {
        // Load 128x16 tiles of A and W (K-contiguous in both), 512 float4 each.
#pragma unroll
        for (int i = 0; i < 2; i++) {
            int idx = tid + i * 256;      // 0..511
            int row = idx >> 2;           // 0..127
            int kq  = (idx & 3) * 4;      // 0,4,8,12
            float4 va = *(const float4*)&A[(size_t)(rowBase + row) * K + k0 + kq];
            As[kq + 0][row] = va.x; As[kq + 1][row] = va.y;
            As[kq + 2][row] = va.z; As[kq + 3][row] = va.w;
            float4 vw = *(const float4*)&W[(size_t)(colBase + row) * K + k0 + kq];
            Ws[kq + 0][row] = vw.x; Ws[kq + 1][row] = vw.y;
            Ws[kq + 2][row] = vw.z; Ws[kq + 3][row] = vw.w;
        }
        __syncthreads();

#pragma unroll
        for (int kk = 0; kk < GBK; kk++) {
            float a[8], b[8];
#pragma unroll
            for (int i = 0; i < 8; i++) a[i] = As[kk][ty * 8 + i];
#pragma unroll
            for (int j = 0; j < 8; j++) b[j] = Ws[kk][tx * 8 + j];
#pragma unroll
            for (int i = 0; i < 8; i++)
#pragma unroll
                for (int j = 0; j < 8; j++)
                    acc[i][j] = fmaf(a[i], b[j], acc[i][j]);
        }
        __syncthreads();
    }

#pragma unroll
    for (int i = 0; i < 8; i++) {
        int row = rowBase + ty * 8 + i;
#pragma unroll
        for (int j = 0; j < 8; j += 4) {
            int col = colBase + tx * 8 + j;
            float4 o;
            o.x = acc[i][j + 0] + bias[col + 0];
            o.y = acc[i][j + 1] + bias[col + 1];
            o.z = acc[i][j + 2] + bias[col + 2];
            o.w = acc[i][j + 3] + bias[col + 3];
            *(float4*)&C[(size_t)row * N + col] = o;
        }
    }
}

// ---------------------------------------------------------------------------
// Flash attention, fp32, causal + additive key-padding mask.
// One block = one (b,h) and a 64-query tile. 256 threads, 4x4 micro-tiles.
// ---------------------------------------------------------------------------
struct AttnSmem {
    float Qs[64][68];
    float Ks[64][68];
    float Vs[64][68];
    float Ps[64][68];
    float pads[64];
};

__global__ __launch_bounds__(256) void attn_kernel(
    const float* __restrict__ Q, const float* __restrict__ Kb,
    const float* __restrict__ Vb, const int* __restrict__ msk,
    float* __restrict__ Y)
{
    extern __shared__ char smem_raw[];
    AttnSmem* sm = (AttnSmem*)smem_raw;

    const int qt  = blockIdx.x;          // query tile (0..31)
    const int bh  = blockIdx.y;          // 0..31
    const int b   = bh / HH;
    const int h   = bh % HH;
    const int tid = threadIdx.x;
    const int tx  = tid & 15;
    const int ty  = tid >> 4;

    // Load Q tile (64 x 64) into smem
    const size_t qbase = ((size_t)b * LL + (size_t)qt * 64) * DD + h * DH;
#pragma unroll
    for (int i = 0; i < 4; i++) {
        int idx = tid + i * 256;         // 0..1023
        int r = idx >> 4;                // 0..63
        int c = (idx & 15) * 4;          // 0..60
        *(float4*)&sm->Qs[r][c] = *(const float4*)&Q[qbase + (size_t)r * DD + c];
    }

    float m_i[4], l_i[4], acc[4][4];
#pragma unroll
    for (int i = 0; i < 4; i++) {
        m_i[i] = -1e30f;
        l_i[i] = 0.0f;
#pragma unroll
        for (int j = 0; j < 4; j++) acc[i][j] = 0.0f;
    }

    const float scale = 0.125f;          // 1/sqrt(64)

    for (int jt = 0; jt <= qt; jt++) {
        const size_t kbase = ((size_t)b * LL + (size_t)jt * 64) * DD + h * DH;
#pragma unroll
        for (int i = 0; i < 4; i++) {
            int idx = tid + i * 256;
            int r = idx >> 4;
            int c = (idx & 15) * 4;
            *(float4*)&sm->Ks[r][c] = *(const float4*)&Kb[kbase + (size_t)r * DD + c];
            *(float4*)&sm->Vs[r][c] = *(const float4*)&Vb[kbase + (size_t)r * DD + c];
        }
        if (tid < 64) {
            sm->pads[tid] = (1.0f - (float)msk[b * LL + jt * 64 + tid]) * NEGV;
        }
        __syncthreads();

        // S = Qs @ Ks^T (rows ty*4.., cols tx*4..)
        float s[4][4];
#pragma unroll
        for (int i = 0; i < 4; i++)
#pragma unroll
            for (int j = 0; j < 4; j++) s[i][j] = 0.0f;

#pragma unroll 8
        for (int d = 0; d < 64; d++) {
            float qv[4], kv[4];
#pragma unroll
            for (int i = 0; i < 4; i++) qv[i] = sm->Qs[ty * 4 + i][d];
#pragma unroll
            for (int j = 0; j < 4; j++) kv[j] = sm->Ks[tx * 4 + j][d];
#pragma unroll
            for (int i = 0; i < 4; i++)
#pragma unroll
                for (int j = 0; j < 4; j++)
                    s[i][j] = fmaf(qv[i], kv[j], s[i][j]);
        }

        // scale + causal mask + pad mask (same order as reference)
#pragma unroll
        for (int i = 0; i < 4; i++) {
            int qg = qt * 64 + ty * 4 + i;
#pragma unroll
            for (int j = 0; j < 4; j++) {
                int kg = jt * 64 + tx * 4 + j;
                float v = s[i][j] * scale;
                if (kg > qg) v = NEGV;
                v += sm->pads[tx * 4 + j];
                s[i][j] = v;
            }
        }

        // online softmax (row groups of 16 lanes share a row set)
#pragma unroll
        for (int i = 0; i < 4; i++) {
            float mx = fmaxf(fmaxf(s[i][0], s[i][1]), fmaxf(s[i][2], s[i][3]));
#pragma unroll
            for (int o = 8; o >= 1; o >>= 1)
                mx = fmaxf(mx, __shfl_xor_sync(0xffffffffu, mx, o));
            float m_new = fmaxf(m_i[i], mx);
            float alpha = __expf(m_i[i] - m_new);
            float rs = 0.0f;
#pragma unroll
            for (int j = 0; j < 4; j++) {
                s[i][j] = __expf(s[i][j] - m_new);
                rs += s[i][j];
            }
#pragma unroll
            for (int o = 8; o >= 1; o >>= 1)
                rs += __shfl_xor_sync(0xffffffffu, rs, o);
            l_i[i] = l_i[i] * alpha + rs;
            m_i[i] = m_new;
#pragma unroll
            for (int j = 0; j < 4; j++) acc[i][j] *= alpha;
        }

        // stage P through smem for the PV product
#pragma unroll
        for (int i = 0; i < 4; i++)
#pragma unroll
            for (int j = 0; j < 4; j++)
                sm->Ps[ty * 4 + i][tx * 4 + j] = s[i][j];
        __syncthreads();

        // O += P @ V
#pragma unroll 8
        for (int k = 0; k < 64; k++) {
            float pv[4], vv[4];
#pragma unroll
            for (int i = 0; i < 4; i++) pv[i] = sm->Ps[ty * 4 + i][k];
#pragma unroll
            for (int j = 0; j < 4; j++) vv[j] = sm->Vs[k][tx * 4 + j];
#pragma unroll
            for (int i = 0; i < 4; i++)
#pragma unroll
                for (int j = 0; j < 4; j++)
                    acc[i][j] = fmaf(pv[i], vv[j], acc[i][j]);
        }
        __syncthreads();
    }

    // finalize + write Y (layout: (B, L, H*DH) so projection GEMM reads it flat)
#pragma unroll
    for (int i = 0; i < 4; i++) {
        int q = qt * 64 + ty * 4 + i;
        float inv = 1.0f / l_i[i];
        size_t obase = ((size_t)b * LL + q) * DD + h * DH + tx * 4;
        float4 o;
        o.x = acc[i][0] * inv;
        o.y = acc[i][1] * inv;
        o.z = acc[i][2] * inv;
        o.w = acc[i][3] * inv;
        *(float4*)&Y[obase] = o;
    }
}

// ---------------------------------------------------------------------------
extern "C" void kernel_launch(void* const* d_in, const int* in_sizes, int n_in,
                              void* d_out, int out_size)
{
    const float* x  = (const float*)d_in[0];
    const int*   m  = (const int*)d_in[1];
    const float* Wq = (const float*)d_in[2];
    const float* bq = (const float*)d_in[3];
    const float* Wk = (const float*)d_in[4];
    const float* bk = (const float*)d_in[5];
    const float* Wv = (const float*)d_in[6];
    const float* bv = (const float*)d_in[7];
    const float* Wp = (const float*)d_in[8];
    const float* bp = (const float*)d_in[9];
    float* out = (float*)d_out;

    float *gQ, *gK, *gV, *gY;
    cudaGetSymbolAddress((void**)&gQ, g_Q);
    cudaGetSymbolAddress((void**)&gK, g_K);
    cudaGetSymbolAddress((void**)&gV, g_V);
    cudaGetSymbolAddress((void**)&gY, g_Y);

    static bool attr_set = false;
    if (!attr_set) {
        cudaFuncSetAttribute(attn_kernel,
                             cudaFuncAttributeMaxDynamicSharedMemorySize,
                             (int)sizeof(AttnSmem));
        attr_set = true;
    }

    const int M = BB * LL;               // 4096
    dim3 ggrid(DD / GBN, M / GBM);       // (8, 32)

    gemm_bias<<<ggrid, 256>>>(x, Wq, bq, gQ, M, DD, DD);
    gemm_bias<<<ggrid, 256>>>(x, Wk, bk, gK, M, DD, DD);
    gemm_bias<<<ggrid, 256>>>(x, Wv, bv, gV, M, DD, DD);

    dim3 agrid(LL / 64, BB * HH);        // (32, 32)
    attn_kernel<<<agrid, 256, sizeof(AttnSmem)>>>(gQ, gK, gV, m, gY);

    gemm_bias<<<ggrid, 256>>>(gY, Wp, bp, out, M, DD, DD);
}

// round 5
// speedup vs baseline: 1.7825x; 1.7825x over previous
#include <cuda_runtime.h>
#include <cuda_bf16.h>
#include <cstdint>
#include <math.h>

#define BB 2
#define LL 2048
#define DD 1024
#define HH 16
#define DH 64
#define NEGV -10000.0f

#define NTOK (BB * LL)          // 4096
#define NELT (BB * LL * DD)     // 4194304
#define WELT (DD * DD)          // 1048576

// ---------------------------------------------------------------------------
// Scratch (__device__ globals per allocation rules)
// ---------------------------------------------------------------------------
__device__ float g_Q[NELT];
__device__ float g_K[NELT];
__device__ float g_V[NELT];
__device__ float g_Y[NELT];
__device__ __nv_bfloat16 g_Ahi[NELT];
__device__ __nv_bfloat16 g_Alo[NELT];
__device__ __nv_bfloat16 g_Whi[4 * WELT];
__device__ __nv_bfloat16 g_Wlo[4 * WELT];

// ---------------------------------------------------------------------------
// PTX helpers (non-'a' features only: ldmatrix sm_75+, mma.sync bf16 sm_80+)
// ---------------------------------------------------------------------------
__device__ __forceinline__ uint32_t smem_u32(const void* p) {
    uint32_t a;
    asm("{ .reg .u64 t; cvta.to.shared.u64 t, %1; cvt.u32.u64 %0, t; }"
        : "=r"(a) : "l"(p));
    return a;
}

#define LDM4(r0, r1, r2, r3, addr) \
    asm volatile("ldmatrix.sync.aligned.m8n8.x4.shared.b16 {%0,%1,%2,%3}, [%4];" \
                 : "=r"(r0), "=r"(r1), "=r"(r2), "=r"(r3) : "r"(addr))

#define MMA16816(acc, a, b0, b1) \
    asm volatile("mma.sync.aligned.m16n8k16.row.col.f32.bf16.bf16.f32 " \
                 "{%0,%1,%2,%3}, {%4,%5,%6,%7}, {%8,%9}, {%0,%1,%2,%3};" \
                 : "+f"((acc)[0]), "+f"((acc)[1]), "+f"((acc)[2]), "+f"((acc)[3]) \
                 : "r"((a)[0]), "r"((a)[1]), "r"((a)[2]), "r"((a)[3]), \
                   "r"(b0), "r"(b1))

// ---------------------------------------------------------------------------
// fp32 -> bf16 hi/lo split
// ---------------------------------------------------------------------------
__global__ __launch_bounds__(256) void conv_split(
    const float* __restrict__ src, __nv_bfloat16* __restrict__ hi,
    __nv_bfloat16* __restrict__ lo, int n)
{
    int idx = (blockIdx.x * 256 + threadIdx.x) * 4;
    if (idx >= n) return;
    float4 v = *(const float4*)&src[idx];
    __nv_bfloat16 h[4], l[4];
    float f[4] = {v.x, v.y, v.z, v.w};
#pragma unroll
    for (int u = 0; u < 4; u++) {
        h[u] = __float2bfloat16(f[u]);
        l[u] = __float2bfloat16(f[u] - __bfloat162float(h[u]));
    }
    *(uint2*)&hi[idx] = *(uint2*)h;
    *(uint2*)&lo[idx] = *(uint2*)l;
}

// ---------------------------------------------------------------------------
// mma.sync bf16 GEMM: C[M,N] = A[M,K] @ W[N,K]^T + bias (hi/lo 3-term)
// Tile 128x128, BK=64. 256 threads = 8 warps, warp tile 32(M) x 64(N).
// smem pitch 72 bf16 = 144B: 8 consecutive rows -> word offsets 0,4,8,...,28
// (mod 32), so each ldmatrix 8-row fetch covers all 32 banks exactly once.
// ---------------------------------------------------------------------------
#define GPITCH 72
#define GTILE  (128 * GPITCH)            // bf16 units per tile
#define GEMM_SMEM (4 * GTILE * 2)        // 73728 bytes

__global__ __launch_bounds__(256) void gemm_mma(
    const __nv_bfloat16* __restrict__ Ahi, const __nv_bfloat16* __restrict__ Alo,
    const __nv_bfloat16* __restrict__ Bhi, const __nv_bfloat16* __restrict__ Blo,
    const float* __restrict__ bias, float* __restrict__ C,
    int M, int N, int K)
{
    extern __shared__ __nv_bfloat16 sm[];
    __nv_bfloat16* tiles[4] = {sm, sm + GTILE, sm + 2 * GTILE, sm + 3 * GTILE};

    const int tid  = threadIdx.x;
    const int lane = tid & 31;
    const int wid  = tid >> 5;
    const int wm   = (wid >> 1) * 32;    // warp M offset (0,32,64,96)
    const int wn   = (wid & 1) * 64;     // warp N offset (0,64)
    const int rowBase = blockIdx.y * 128;
    const int colBase = blockIdx.x * 128;

    const uint32_t sbase = smem_u32(sm);
    const uint32_t sAh = sbase;
    const uint32_t sAl = sbase + GTILE * 2;
    const uint32_t sBh = sbase + 2 * GTILE * 2;
    const uint32_t sBl = sbase + 3 * GTILE * 2;

    // ldmatrix lane addressing (bf16-unit offsets, *2 for bytes)
    // A x4: lanes 0-15 -> rows 0-15 @ k0, lanes 16-31 -> rows 0-15 @ k+8
    const uint32_t aOff = ((uint32_t)(wm + (lane & 15)) * GPITCH + ((lane >> 4) << 3)) * 2;
    // B x4: lanes 0-7 cols n0-7 @k0, 8-15 cols n0-7 @k8, 16-23 n8-15 @k0, 24-31 n8-15 @k8
    const uint32_t bOff = ((uint32_t)(wn + (lane & 7) + ((lane >> 4) << 3)) * GPITCH
                          + (((lane >> 3) & 1) << 3)) * 2;

    float acc[2][8][4];
#pragma unroll
    for (int i = 0; i < 2; i++)
#pragma unroll
        for (int j = 0; j < 8; j++)
#pragma unroll
            for (int v = 0; v < 4; v++) acc[i][j][v] = 0.0f;

    for (int k0 = 0; k0 < K; k0 += 64) {
        // load 4 tiles of 128 rows x 64 bf16 (128B/row), coalesced uint4
        const __nv_bfloat16* srcs[4] = {Ahi, Alo, Bhi, Blo};
        const int rbs[4] = {rowBase, rowBase, colBase, colBase};
#pragma unroll
        for (int t = 0; t < 4; t++) {
            const __nv_bfloat16* s = srcs[t];
            __nv_bfloat16* dst = tiles[t];
            const int rb = rbs[t];
#pragma unroll
            for (int i = 0; i < 4; i++) {
                int idx = tid + i * 256;     // 0..1023
                int r = idx >> 3;            // 0..127
                int c = idx & 7;             // 16B chunk
                uint4 v = *(const uint4*)(s + (size_t)(rb + r) * K + k0 + c * 8);
                *(uint4*)(dst + r * GPITCH + c * 8) = v;
            }
        }
        __syncthreads();

#pragma unroll
        for (int kk = 0; kk < 4; kk++) {     // four k16 steps
            const uint32_t kByte = kk * 32;  // 16 bf16 = 32B
            uint32_t ah[2][4], al[2][4];
#pragma unroll
            for (int mi = 0; mi < 2; mi++) {
                uint32_t ao = aOff + mi * 16 * GPITCH * 2 + kByte;
                LDM4(ah[mi][0], ah[mi][1], ah[mi][2], ah[mi][3], sAh + ao);
                LDM4(al[mi][0], al[mi][1], al[mi][2], al[mi][3], sAl + ao);
            }
#pragma unroll
            for (int nb2 = 0; nb2 < 4; nb2++) {
                uint32_t bo = bOff + nb2 * 16 * GPITCH * 2 + kByte;
                uint32_t bh[4], bl[4];
                LDM4(bh[0], bh[1], bh[2], bh[3], sBh + bo);
                LDM4(bl[0], bl[1], bl[2], bl[3], sBl + bo);
#pragma unroll
                for (int mi = 0; mi < 2; mi++) {
                    MMA16816(acc[mi][nb2 * 2 + 0], ah[mi], bh[0], bh[1]);
                    MMA16816(acc[mi][nb2 * 2 + 1], ah[mi], bh[2], bh[3]);
                    MMA16816(acc[mi][nb2 * 2 + 0], ah[mi], bl[0], bl[1]);
                    MMA16816(acc[mi][nb2 * 2 + 1], ah[mi], bl[2], bl[3]);
                    MMA16816(acc[mi][nb2 * 2 + 0], al[mi], bh[0], bh[1]);
                    MMA16816(acc[mi][nb2 * 2 + 1], al[mi], bh[2], bh[3]);
                }
            }
        }
        __syncthreads();
    }

    // epilogue: d0,d1 -> (row g, col tc,tc+1); d2,d3 -> (row g+8)
    const int g  = lane >> 2;
    const int tc = (lane & 3) * 2;
#pragma unroll
    for (int mi = 0; mi < 2; mi++) {
#pragma unroll
        for (int nb = 0; nb < 8; nb++) {
            int col = colBase + wn + nb * 8 + tc;
            float b0 = bias[col], b1 = bias[col + 1];
            int row0 = rowBase + wm + mi * 16 + g;
            float2 o0 = {acc[mi][nb][0] + b0, acc[mi][nb][1] + b1};
            *(float2*)&C[(size_t)row0 * N + col] = o0;
            float2 o1 = {acc[mi][nb][2] + b0, acc[mi][nb][3] + b1};
            *(float2*)&C[(size_t)(row0 + 8) * N + col] = o1;
        }
    }
}

// ---------------------------------------------------------------------------
// Flash attention, fp32, causal + key-padding. K tile TRANSPOSED in smem
// (kv read becomes one conflict-free LDS.128; was 4x 8-way-conflicted LDS).
// ---------------------------------------------------------------------------
struct AttnSmem {
    float Qs[64][68];   // [qrow][d]
    float Kt[64][68];   // [d][kcol]   (transposed)
    float Vs[64][68];   // [krow][d]
    float Ps[64][68];   // [qrow][kcol]
    float pads[64];
};

__global__ __launch_bounds__(256) void attn_kernel(
    const float* __restrict__ Q, const float* __restrict__ Kb,
    const float* __restrict__ Vb, const int* __restrict__ msk,
    float* __restrict__ Y)
{
    extern __shared__ char smem_raw[];
    AttnSmem* sm = (AttnSmem*)smem_raw;

    const int qt  = gridDim.x - 1 - blockIdx.x;   // heavy tiles first
    const int bh  = blockIdx.y;
    const int b   = bh / HH;
    const int h   = bh % HH;
    const int tid = threadIdx.x;
    const int tx  = tid & 15;
    const int ty  = tid >> 4;

    const size_t qbase = ((size_t)b * LL + (size_t)qt * 64) * DD + h * DH;
#pragma unroll
    for (int i = 0; i < 4; i++) {
        int idx = tid + i * 256;
        int r = idx >> 4;
        int c = (idx & 15) * 4;
        *(float4*)&sm->Qs[r][c] = *(const float4*)&Q[qbase + (size_t)r * DD + c];
    }

    float m_i[4], l_i[4], acc[4][4];
#pragma unroll
    for (int i = 0; i < 4; i++) {
        m_i[i] = -1e30f;
        l_i[i] = 0.0f;
#pragma unroll
        for (int j = 0; j < 4; j++) acc[i][j] = 0.0f;
    }

    const float scale = 0.125f;

    for (int jt = 0; jt <= qt; jt++) {
        const size_t kbase = ((size_t)b * LL + (size_t)jt * 64) * DD + h * DH;
#pragma unroll
        for (int i = 0; i < 4; i++) {
            int idx = tid + i * 256;
            int r = idx >> 4;          // key index
            int c = (idx & 15) * 4;    // dh
            float4 kv = *(const float4*)&Kb[kbase + (size_t)r * DD + c];
            sm->Kt[c + 0][r] = kv.x;   // transposed store
            sm->Kt[c + 1][r] = kv.y;
            sm->Kt[c + 2][r] = kv.z;
            sm->Kt[c + 3][r] = kv.w;
            *(float4*)&sm->Vs[r][c] = *(const float4*)&Vb[kbase + (size_t)r * DD + c];
        }
        if (tid < 64) {
            sm->pads[tid] = (1.0f - (float)msk[b * LL + jt * 64 + tid]) * NEGV;
        }
        __syncthreads();

        float s[4][4];
#pragma unroll
        for (int i = 0; i < 4; i++)
#pragma unroll
            for (int j = 0; j < 4; j++) s[i][j] = 0.0f;

#pragma unroll 8
        for (int d = 0; d < 64; d++) {
            float4 kv = *(const float4*)&sm->Kt[d][tx * 4];
            float qv[4];
#pragma unroll
            for (int i = 0; i < 4; i++) qv[i] = sm->Qs[ty * 4 + i][d];
#pragma unroll
            for (int i = 0; i < 4; i++) {
                s[i][0] = fmaf(qv[i], kv.x, s[i][0]);
                s[i][1] = fmaf(qv[i], kv.y, s[i][1]);
                s[i][2] = fmaf(qv[i], kv.z, s[i][2]);
                s[i][3] = fmaf(qv[i], kv.w, s[i][3]);
            }
        }

#pragma unroll
        for (int i = 0; i < 4; i++) {
            int qg = qt * 64 + ty * 4 + i;
#pragma unroll
            for (int j = 0; j < 4; j++) {
                int kg = jt * 64 + tx * 4 + j;
                float v = s[i][j] * scale;
                if (kg > qg) v = NEGV;
                v += sm->pads[tx * 4 + j];
                s[i][j] = v;
            }
        }

#pragma unroll
        for (int i = 0; i < 4; i++) {
            float mx = fmaxf(fmaxf(s[i][0], s[i][1]), fmaxf(s[i][2], s[i][3]));
#pragma unroll
            for (int o = 8; o >= 1; o >>= 1)
                mx = fmaxf(mx, __shfl_xor_sync(0xffffffffu, mx, o));
            float m_new = fmaxf(m_i[i], mx);
            float alpha = __expf(m_i[i] - m_new);
            float rs = 0.0f;
#pragma unroll
            for (int j = 0; j < 4; j++) {
                s[i][j] = __expf(s[i][j] - m_new);
                rs += s[i][j];
            }
#pragma unroll
            for (int o = 8; o >= 1; o >>= 1)
                rs += __shfl_xor_sync(0xffffffffu, rs, o);
            l_i[i] = l_i[i] * alpha + rs;
            m_i[i] = m_new;
#pragma unroll
            for (int j = 0; j < 4; j++) acc[i][j] *= alpha;
        }

#pragma unroll
        for (int i = 0; i < 4; i++)
#pragma unroll
            for (int j = 0; j < 4; j++)
                sm->Ps[ty * 4 + i][tx * 4 + j] = s[i][j];
        __syncthreads();

#pragma unroll 8
        for (int k = 0; k < 64; k++) {
            float4 vv = *(const float4*)&sm->Vs[k][tx * 4];
            float pv[4];
#pragma unroll
            for (int i = 0; i < 4; i++) pv[i] = sm->Ps[ty * 4 + i][k];
#pragma unroll
            for (int i = 0; i < 4; i++) {
                acc[i][0] = fmaf(pv[i], vv.x, acc[i][0]);
                acc[i][1] = fmaf(pv[i], vv.y, acc[i][1]);
                acc[i][2] = fmaf(pv[i], vv.z, acc[i][2]);
                acc[i][3] = fmaf(pv[i], vv.w, acc[i][3]);
            }
        }
        __syncthreads();
    }

#pragma unroll
    for (int i = 0; i < 4; i++) {
        int q = qt * 64 + ty * 4 + i;
        float inv = 1.0f / l_i[i];
        size_t obase = ((size_t)b * LL + q) * DD + h * DH + tx * 4;
        float4 o;
        o.x = acc[i][0] * inv;
        o.y = acc[i][1] * inv;
        o.z = acc[i][2] * inv;
        o.w = acc[i][3] * inv;
        *(float4*)&Y[obase] = o;
    }
}

// ---------------------------------------------------------------------------
extern "C" void kernel_launch(void* const* d_in, const int* in_sizes, int n_in,
                              void* d_out, int out_size)
{
    const float* x  = (const float*)d_in[0];
    const int*   m  = (const int*)d_in[1];
    const float* Wq = (const float*)d_in[2];
    const float* bq = (const float*)d_in[3];
    const float* Wk = (const float*)d_in[4];
    const float* bk = (const float*)d_in[5];
    const float* Wv = (const float*)d_in[6];
    const float* bv = (const float*)d_in[7];
    const float* Wp = (const float*)d_in[8];
    const float* bp = (const float*)d_in[9];
    float* out = (float*)d_out;

    float *gQ, *gK, *gV, *gY;
    __nv_bfloat16 *aHi, *aLo, *wHi, *wLo;
    cudaGetSymbolAddress((void**)&gQ, g_Q);
    cudaGetSymbolAddress((void**)&gK, g_K);
    cudaGetSymbolAddress((void**)&gV, g_V);
    cudaGetSymbolAddress((void**)&gY, g_Y);
    cudaGetSymbolAddress((void**)&aHi, g_Ahi);
    cudaGetSymbolAddress((void**)&aLo, g_Alo);
    cudaGetSymbolAddress((void**)&wHi, g_Whi);
    cudaGetSymbolAddress((void**)&wLo, g_Wlo);

    static bool attr_set = false;
    if (!attr_set) {
        cudaFuncSetAttribute(attn_kernel,
                             cudaFuncAttributeMaxDynamicSharedMemorySize,
                             (int)sizeof(AttnSmem));
        cudaFuncSetAttribute(gemm_mma,
                             cudaFuncAttributeMaxDynamicSharedMemorySize,
                             GEMM_SMEM);
        attr_set = true;
    }

    // bf16 hi/lo conversions
    conv_split<<<NELT / 4 / 256, 256>>>(x, aHi, aLo, NELT);
    conv_split<<<WELT / 4 / 256, 256>>>(Wq, wHi + 0 * WELT, wLo + 0 * WELT, WELT);
    conv_split<<<WELT / 4 / 256, 256>>>(Wk, wHi + 1 * WELT, wLo + 1 * WELT, WELT);
    conv_split<<<WELT / 4 / 256, 256>>>(Wv, wHi + 2 * WELT, wLo + 2 * WELT, WELT);
    conv_split<<<WELT / 4 / 256, 256>>>(Wp, wHi + 3 * WELT, wLo + 3 * WELT, WELT);

    dim3 ggrid(DD / 128, NTOK / 128);  // (8, 32)
    gemm_mma<<<ggrid, 256, GEMM_SMEM>>>(aHi, aLo, wHi + 0 * WELT, wLo + 0 * WELT,
                                        bq, gQ, NTOK, DD, DD);
    gemm_mma<<<ggrid, 256, GEMM_SMEM>>>(aHi, aLo, wHi + 1 * WELT, wLo + 1 * WELT,
                                        bk, gK, NTOK, DD, DD);
    gemm_mma<<<ggrid, 256, GEMM_SMEM>>>(aHi, aLo, wHi + 2 * WELT, wLo + 2 * WELT,
                                        bv, gV, NTOK, DD, DD);

    dim3 agrid(LL / 64, BB * HH);      // (32, 32)
    attn_kernel<<<agrid, 256, sizeof(AttnSmem)>>>(gQ, gK, gV, m, gY);

    conv_split<<<NELT / 4 / 256, 256>>>(gY, aHi, aLo, NELT);
    gemm_mma<<<ggrid, 256, GEMM_SMEM>>>(aHi, aLo, wHi + 3 * WELT, wLo + 3 * WELT,
                                        bp, out, NTOK, DD, DD);
}

// round 6
// speedup vs baseline: 2.9560x; 1.6583x over previous
#include <cuda_runtime.h>
#include <cuda_bf16.h>
#include <cstdint>
#include <math.h>

#define BB 2
#define LL 2048
#define DD 1024
#define HH 16
#define DH 64
#define NEGV -10000.0f

#define NTOK (BB * LL)          // 4096
#define NELT (BB * LL * DD)     // 4194304
#define WELT (DD * DD)          // 1048576

typedef __nv_bfloat16 bf16;
typedef __nv_bfloat162 bf162;

// ---------------------------------------------------------------------------
// Scratch (__device__ globals per allocation rules) — all bf16 hi/lo pairs
// ---------------------------------------------------------------------------
__device__ bf16 g_Xh[NELT];
__device__ bf16 g_Xl[NELT];
__device__ bf16 g_Whi[4 * WELT];
__device__ bf16 g_Wlo[4 * WELT];
__device__ bf16 g_Qh[NELT];
__device__ bf16 g_Ql[NELT];
__device__ bf16 g_Kh[NELT];
__device__ bf16 g_Kl[NELT];
__device__ bf16 g_Vh[NELT];
__device__ bf16 g_Vl[NELT];
__device__ bf16 g_Yh[NELT];
__device__ bf16 g_Yl[NELT];

// ---------------------------------------------------------------------------
// PTX helpers (non-'a' features: ldmatrix sm_75+, mma.sync bf16 sm_80+)
// ---------------------------------------------------------------------------
__device__ __forceinline__ uint32_t smem_u32(const void* p) {
    uint32_t a;
    asm("{ .reg .u64 t; cvta.to.shared.u64 t, %1; cvt.u32.u64 %0, t; }"
        : "=r"(a) : "l"(p));
    return a;
}

#define LDM4(r0, r1, r2, r3, addr) \
    asm volatile("ldmatrix.sync.aligned.m8n8.x4.shared.b16 {%0,%1,%2,%3}, [%4];" \
                 : "=r"(r0), "=r"(r1), "=r"(r2), "=r"(r3) : "r"(addr))

#define LDMT4(r0, r1, r2, r3, addr) \
    asm volatile("ldmatrix.sync.aligned.m8n8.x4.trans.shared.b16 {%0,%1,%2,%3}, [%4];" \
                 : "=r"(r0), "=r"(r1), "=r"(r2), "=r"(r3) : "r"(addr))

#define MMA16816(acc, a, b0, b1) \
    asm volatile("mma.sync.aligned.m16n8k16.row.col.f32.bf16.bf16.f32 " \
                 "{%0,%1,%2,%3}, {%4,%5,%6,%7}, {%8,%9}, {%0,%1,%2,%3};" \
                 : "+f"((acc)[0]), "+f"((acc)[1]), "+f"((acc)[2]), "+f"((acc)[3]) \
                 : "r"((a)[0]), "r"((a)[1]), "r"((a)[2]), "r"((a)[3]), \
                   "r"(b0), "r"(b1))

// split a,b into packed bf16 hi pair + residual lo pair
__device__ __forceinline__ void split2(float a, float b, uint32_t& hi, uint32_t& lo) {
    bf162 h = __floats2bfloat162_rn(a, b);
    float ra = a - __bfloat162float(h.x);
    float rb = b - __bfloat162float(h.y);
    bf162 l = __floats2bfloat162_rn(ra, rb);
    hi = *(uint32_t*)&h;
    lo = *(uint32_t*)&l;
}

// ---------------------------------------------------------------------------
// fp32 -> bf16 hi/lo split
// ---------------------------------------------------------------------------
__global__ __launch_bounds__(256) void conv_split(
    const float* __restrict__ src, bf16* __restrict__ hi,
    bf16* __restrict__ lo, int n)
{
    int idx = (blockIdx.x * 256 + threadIdx.x) * 4;
    if (idx >= n) return;
    float4 v = *(const float4*)&src[idx];
    bf16 h[4], l[4];
    float f[4] = {v.x, v.y, v.z, v.w};
#pragma unroll
    for (int u = 0; u < 4; u++) {
        h[u] = __float2bfloat16(f[u]);
        l[u] = __float2bfloat16(f[u] - __bfloat162float(h[u]));
    }
    *(uint2*)&hi[idx] = *(uint2*)h;
    *(uint2*)&lo[idx] = *(uint2*)l;
}

// ---------------------------------------------------------------------------
// mma.sync bf16 GEMM: C[M,N] = A[M,K] @ W[N,K]^T + bias (hi/lo 3-term)
// Tile 128x128, BK=64, 8 warps (4Mx2N), warp tile 32x64. Pitch 72 bf16.
// Output: fp32 C, or bf16 hi/lo split pair (Chi/Clo) when Chi != nullptr.
// ---------------------------------------------------------------------------
#define GPITCH 72
#define GTILE  (128 * GPITCH)
#define GEMM_SMEM (4 * GTILE * 2)        // 73728 bytes

__global__ __launch_bounds__(256) void gemm_mma(
    const bf16* __restrict__ Ahi, const bf16* __restrict__ Alo,
    const bf16* __restrict__ Bhi, const bf16* __restrict__ Blo,
    const float* __restrict__ bias, float* __restrict__ C,
    bf16* __restrict__ Chi, bf16* __restrict__ Clo,
    int M, int N, int K)
{
    extern __shared__ bf16 sm[];
    bf16* tiles[4] = {sm, sm + GTILE, sm + 2 * GTILE, sm + 3 * GTILE};

    const int tid  = threadIdx.x;
    const int lane = tid & 31;
    const int wid  = tid >> 5;
    const int wm   = (wid >> 1) * 32;
    const int wn   = (wid & 1) * 64;
    const int rowBase = blockIdx.y * 128;
    const int colBase = blockIdx.x * 128;

    const uint32_t sbase = smem_u32(sm);
    const uint32_t sAh = sbase;
    const uint32_t sAl = sbase + GTILE * 2;
    const uint32_t sBh = sbase + 2 * GTILE * 2;
    const uint32_t sBl = sbase + 3 * GTILE * 2;

    const uint32_t aOff = ((uint32_t)(wm + (lane & 15)) * GPITCH + ((lane >> 4) << 3)) * 2;
    const uint32_t bOff = ((uint32_t)(wn + (lane & 7) + ((lane >> 4) << 3)) * GPITCH
                          + (((lane >> 3) & 1) << 3)) * 2;

    float acc[2][8][4];
#pragma unroll
    for (int i = 0; i < 2; i++)
#pragma unroll
        for (int j = 0; j < 8; j++)
#pragma unroll
            for (int v = 0; v < 4; v++) acc[i][j][v] = 0.0f;

    for (int k0 = 0; k0 < K; k0 += 64) {
        const bf16* srcs[4] = {Ahi, Alo, Bhi, Blo};
        const int rbs[4] = {rowBase, rowBase, colBase, colBase};
#pragma unroll
        for (int t = 0; t < 4; t++) {
            const bf16* s = srcs[t];
            bf16* dst = tiles[t];
            const int rb = rbs[t];
#pragma unroll
            for (int i = 0; i < 4; i++) {
                int idx = tid + i * 256;
                int r = idx >> 3;
                int c = idx & 7;
                uint4 v = *(const uint4*)(s + (size_t)(rb + r) * K + k0 + c * 8);
                *(uint4*)(dst + r * GPITCH + c * 8) = v;
            }
        }
        __syncthreads();

#pragma unroll
        for (int kk = 0; kk < 4; kk++) {
            const uint32_t kByte = kk * 32;
            uint32_t ah[2][4], al[2][4];
#pragma unroll
            for (int mi = 0; mi < 2; mi++) {
                uint32_t ao = aOff + mi * 16 * GPITCH * 2 + kByte;
                LDM4(ah[mi][0], ah[mi][1], ah[mi][2], ah[mi][3], sAh + ao);
                LDM4(al[mi][0], al[mi][1], al[mi][2], al[mi][3], sAl + ao);
            }
#pragma unroll
            for (int nb2 = 0; nb2 < 4; nb2++) {
                uint32_t bo = bOff + nb2 * 16 * GPITCH * 2 + kByte;
                uint32_t bh[4], bl[4];
                LDM4(bh[0], bh[1], bh[2], bh[3], sBh + bo);
                LDM4(bl[0], bl[1], bl[2], bl[3], sBl + bo);
#pragma unroll
                for (int mi = 0; mi < 2; mi++) {
                    MMA16816(acc[mi][nb2 * 2 + 0], ah[mi], bh[0], bh[1]);
                    MMA16816(acc[mi][nb2 * 2 + 1], ah[mi], bh[2], bh[3]);
                    MMA16816(acc[mi][nb2 * 2 + 0], ah[mi], bl[0], bl[1]);
                    MMA16816(acc[mi][nb2 * 2 + 1], ah[mi], bl[2], bl[3]);
                    MMA16816(acc[mi][nb2 * 2 + 0], al[mi], bh[0], bh[1]);
                    MMA16816(acc[mi][nb2 * 2 + 1], al[mi], bh[2], bh[3]);
                }
            }
        }
        __syncthreads();
    }

    const int g  = lane >> 2;
    const int tc = (lane & 3) * 2;
#pragma unroll
    for (int mi = 0; mi < 2; mi++) {
#pragma unroll
        for (int nb = 0; nb < 8; nb++) {
            int col = colBase + wn + nb * 8 + tc;
            float b0 = bias[col], b1 = bias[col + 1];
            int row0 = rowBase + wm + mi * 16 + g;
            float y0 = acc[mi][nb][0] + b0, y1 = acc[mi][nb][1] + b1;
            float y2 = acc[mi][nb][2] + b0, y3 = acc[mi][nb][3] + b1;
            if (Chi) {
                uint32_t h, l;
                split2(y0, y1, h, l);
                *(uint32_t*)&Chi[(size_t)row0 * N + col] = h;
                *(uint32_t*)&Clo[(size_t)row0 * N + col] = l;
                split2(y2, y3, h, l);
                *(uint32_t*)&Chi[(size_t)(row0 + 8) * N + col] = h;
                *(uint32_t*)&Clo[(size_t)(row0 + 8) * N + col] = l;
            } else {
                float2 o0 = {y0, y1};
                *(float2*)&C[(size_t)row0 * N + col] = o0;
                float2 o1 = {y2, y3};
                *(float2*)&C[(size_t)(row0 + 8) * N + col] = o1;
            }
        }
    }
}

// ---------------------------------------------------------------------------
// mma.sync bf16 flash attention (3-term hi/lo for S and PV).
// BQ=128, BK=64, 8 warps (16 q-rows each). P stays in registers (S accum
// fragment == A fragment layout for PV). V via ldmatrix.trans.
// ---------------------------------------------------------------------------
#define AP 72                        // smem pitch (bf16 units)
#define AQH_B 0                      // byte offsets in dynamic smem
#define AQL_B (128 * AP * 2)         // 18432
#define AKH_B (2 * 128 * AP * 2)     // 36864
#define AKL_B (AKH_B + 64 * AP * 2)  // 46080
#define AVH_B (AKL_B + 64 * AP * 2)  // 55296
#define AVL_B (AVH_B + 64 * AP * 2)  // 64512
#define APAD_B (AVL_B + 64 * AP * 2) // 73728
#define ATTN_SMEM (APAD_B + 64 * 4)  // 73984

__global__ __launch_bounds__(256) void attn_mma(
    const bf16* __restrict__ Qh, const bf16* __restrict__ Ql,
    const bf16* __restrict__ Kh, const bf16* __restrict__ Kl,
    const bf16* __restrict__ Vh, const bf16* __restrict__ Vl,
    const int* __restrict__ msk,
    bf16* __restrict__ Yh, bf16* __restrict__ Yl)
{
    extern __shared__ char sraw[];
    float* pads = (float*)(sraw + APAD_B);

    const int tid  = threadIdx.x;
    const int lane = tid & 31;
    const int wid  = tid >> 5;
    const int wm   = wid * 16;            // warp's q-row offset in tile
    const int qt   = gridDim.x - 1 - blockIdx.x;   // heavy tiles first
    const int bh   = blockIdx.y;
    const int b    = bh / HH;
    const int h    = bh % HH;

    const uint32_t sbase = smem_u32(sraw);
    const uint32_t sQH = sbase + AQH_B, sQL = sbase + AQL_B;
    const uint32_t sKH = sbase + AKH_B, sKL = sbase + AKL_B;
    const uint32_t sVH = sbase + AVH_B, sVL = sbase + AVL_B;

    // ---- load Q tile (128 x 64) hi/lo ----
    const size_t qrow0 = (size_t)b * LL + (size_t)qt * 128;
#pragma unroll
    for (int i = 0; i < 4; i++) {
        int idx = tid + i * 256;          // 0..1023
        int r = idx >> 3;                 // 0..127
        int c = idx & 7;
        size_t gsrc = (qrow0 + r) * DD + h * DH + c * 8;
        *(uint4*)(sraw + AQH_B + (r * AP + c * 8) * 2) = *(const uint4*)(Qh + gsrc);
        *(uint4*)(sraw + AQL_B + (r * AP + c * 8) * 2) = *(const uint4*)(Ql + gsrc);
    }

    // ldmatrix lane offsets (bytes)
    const uint32_t aOff = ((uint32_t)(wm + (lane & 15)) * AP + ((lane >> 4) << 3)) * 2;
    const uint32_t bOff = ((uint32_t)((lane & 7) + ((lane >> 4) << 3)) * AP
                          + (((lane >> 3) & 1) << 3)) * 2;
    const uint32_t vOff = ((uint32_t)(((lane >> 3) & 1) * 8 + (lane & 7)) * AP
                          + ((lane >> 4) << 3)) * 2;

    const int g   = lane >> 2;
    const int tc2 = (lane & 3) * 2;
    const int qg0 = qt * 128 + wm + g;
    const int qg1 = qg0 + 8;

    float m0 = -1e30f, m1 = -1e30f, l0 = 0.0f, l1 = 0.0f;
    float oacc[8][4];
#pragma unroll
    for (int i = 0; i < 8; i++)
#pragma unroll
        for (int v = 0; v < 4; v++) oacc[i][v] = 0.0f;

    const float scale = 0.125f;
    const int jtMax = 2 * qt + 1;

    for (int jt = 0; jt <= jtMax; jt++) {
        // ---- load K,V tiles (64 x 64) hi/lo + pads ----
        const size_t krow0 = (size_t)b * LL + (size_t)jt * 64;
#pragma unroll
        for (int i = 0; i < 2; i++) {
            int idx = tid + i * 256;      // 0..511
            int r = idx >> 3;             // 0..63
            int c = idx & 7;
            size_t gsrc = (krow0 + r) * DD + h * DH + c * 8;
            uint32_t so = (r * AP + c * 8) * 2;
            *(uint4*)(sraw + AKH_B + so) = *(const uint4*)(Kh + gsrc);
            *(uint4*)(sraw + AKL_B + so) = *(const uint4*)(Kl + gsrc);
            *(uint4*)(sraw + AVH_B + so) = *(const uint4*)(Vh + gsrc);
            *(uint4*)(sraw + AVL_B + so) = *(const uint4*)(Vl + gsrc);
        }
        if (tid < 64)
            pads[tid] = (1.0f - (float)msk[b * LL + jt * 64 + tid]) * NEGV;
        __syncthreads();

        // ---- S = Q @ K^T (3-term) ----
        float sacc[8][4];
#pragma unroll
        for (int i = 0; i < 8; i++)
#pragma unroll
            for (int v = 0; v < 4; v++) sacc[i][v] = 0.0f;

#pragma unroll
        for (int kk = 0; kk < 4; kk++) {
            const uint32_t kByte = kk * 32;
            uint32_t ah[4], al[4];
            LDM4(ah[0], ah[1], ah[2], ah[3], sQH + aOff + kByte);
            LDM4(al[0], al[1], al[2], al[3], sQL + aOff + kByte);
#pragma unroll
            for (int nb2 = 0; nb2 < 4; nb2++) {
                uint32_t bo = bOff + nb2 * 16 * AP * 2 + kByte;
                uint32_t kh[4], kl[4];
                LDM4(kh[0], kh[1], kh[2], kh[3], sKH + bo);
                LDM4(kl[0], kl[1], kl[2], kl[3], sKL + bo);
                MMA16816(sacc[nb2 * 2 + 0], ah, kh[0], kh[1]);
                MMA16816(sacc[nb2 * 2 + 1], ah, kh[2], kh[3]);
                MMA16816(sacc[nb2 * 2 + 0], ah, kl[0], kl[1]);
                MMA16816(sacc[nb2 * 2 + 1], ah, kl[2], kl[3]);
                MMA16816(sacc[nb2 * 2 + 0], al, kh[0], kh[1]);
                MMA16816(sacc[nb2 * 2 + 1], al, kh[2], kh[3]);
            }
        }

        // ---- scale + causal + pad mask (reference order) ----
#pragma unroll
        for (int nb = 0; nb < 8; nb++) {
            int kgA = jt * 64 + nb * 8 + tc2;
            float p0 = pads[nb * 8 + tc2];
            float p1 = pads[nb * 8 + tc2 + 1];
            float v0 = sacc[nb][0] * scale; if (kgA     > qg0) v0 = NEGV; v0 += p0;
            float v1 = sacc[nb][1] * scale; if (kgA + 1 > qg0) v1 = NEGV; v1 += p1;
            float v2 = sacc[nb][2] * scale; if (kgA     > qg1) v2 = NEGV; v2 += p0;
            float v3 = sacc[nb][3] * scale; if (kgA + 1 > qg1) v3 = NEGV; v3 += p1;
            sacc[nb][0] = v0; sacc[nb][1] = v1; sacc[nb][2] = v2; sacc[nb][3] = v3;
        }

        // ---- online softmax (rows g, g+8; reduce over 4-lane groups) ----
        float rmax0 = -1e30f, rmax1 = -1e30f;
#pragma unroll
        for (int nb = 0; nb < 8; nb++) {
            rmax0 = fmaxf(rmax0, fmaxf(sacc[nb][0], sacc[nb][1]));
            rmax1 = fmaxf(rmax1, fmaxf(sacc[nb][2], sacc[nb][3]));
        }
#pragma unroll
        for (int o = 1; o <= 2; o <<= 1) {
            rmax0 = fmaxf(rmax0, __shfl_xor_sync(0xffffffffu, rmax0, o));
            rmax1 = fmaxf(rmax1, __shfl_xor_sync(0xffffffffu, rmax1, o));
        }
        float m0n = fmaxf(m0, rmax0), m1n = fmaxf(m1, rmax1);
        float a0 = __expf(m0 - m0n), a1 = __expf(m1 - m1n);
        float sum0 = 0.0f, sum1 = 0.0f;
#pragma unroll
        for (int nb = 0; nb < 8; nb++) {
            sacc[nb][0] = __expf(sacc[nb][0] - m0n);
            sacc[nb][1] = __expf(sacc[nb][1] - m0n);
            sacc[nb][2] = __expf(sacc[nb][2] - m1n);
            sacc[nb][3] = __expf(sacc[nb][3] - m1n);
            sum0 += sacc[nb][0] + sacc[nb][1];
            sum1 += sacc[nb][2] + sacc[nb][3];
        }
#pragma unroll
        for (int o = 1; o <= 2; o <<= 1) {
            sum0 += __shfl_xor_sync(0xffffffffu, sum0, o);
            sum1 += __shfl_xor_sync(0xffffffffu, sum1, o);
        }
        l0 = l0 * a0 + sum0; m0 = m0n;
        l1 = l1 * a1 + sum1; m1 = m1n;
#pragma unroll
        for (int nb = 0; nb < 8; nb++) {
            oacc[nb][0] *= a0; oacc[nb][1] *= a0;
            oacc[nb][2] *= a1; oacc[nb][3] *= a1;
        }

        // ---- O += P @ V (3-term, P from registers) ----
#pragma unroll
        for (int kb = 0; kb < 4; kb++) {
            uint32_t pah[4], pal[4];
            split2(sacc[2 * kb][0],     sacc[2 * kb][1],     pah[0], pal[0]);
            split2(sacc[2 * kb][2],     sacc[2 * kb][3],     pah[1], pal[1]);
            split2(sacc[2 * kb + 1][0], sacc[2 * kb + 1][1], pah[2], pal[2]);
            split2(sacc[2 * kb + 1][2], sacc[2 * kb + 1][3], pah[3], pal[3]);
#pragma unroll
            for (int nb2 = 0; nb2 < 4; nb2++) {
                uint32_t vo = vOff + (kb * 16 * AP + nb2 * 16) * 2;
                uint32_t vh[4], vl[4];
                LDMT4(vh[0], vh[1], vh[2], vh[3], sVH + vo);
                LDMT4(vl[0], vl[1], vl[2], vl[3], sVL + vo);
                MMA16816(oacc[nb2 * 2 + 0], pah, vh[0], vh[1]);
                MMA16816(oacc[nb2 * 2 + 1], pah, vh[2], vh[3]);
                MMA16816(oacc[nb2 * 2 + 0], pah, vl[0], vl[1]);
                MMA16816(oacc[nb2 * 2 + 1], pah, vl[2], vl[3]);
                MMA16816(oacc[nb2 * 2 + 0], pal, vh[0], vh[1]);
                MMA16816(oacc[nb2 * 2 + 1], pal, vh[2], vh[3]);
            }
        }
        __syncthreads();   // protect smem tiles before next iteration's loads
    }

    // ---- finalize + write Y hi/lo (layout (B*L, D) for projection GEMM) ----
    float inv0 = 1.0f / l0, inv1 = 1.0f / l1;
    const size_t row0 = qrow0 + wm + g;
#pragma unroll
    for (int nb = 0; nb < 8; nb++) {
        int col = h * DH + nb * 8 + tc2;
        uint32_t hzz, lzz;
        split2(oacc[nb][0] * inv0, oacc[nb][1] * inv0, hzz, lzz);
        *(uint32_t*)&Yh[row0 * DD + col] = hzz;
        *(uint32_t*)&Yl[row0 * DD + col] = lzz;
        split2(oacc[nb][2] * inv1, oacc[nb][3] * inv1, hzz, lzz);
        *(uint32_t*)&Yh[(row0 + 8) * DD + col] = hzz;
        *(uint32_t*)&Yl[(row0 + 8) * DD + col] = lzz;
    }
}

// ---------------------------------------------------------------------------
extern "C" void kernel_launch(void* const* d_in, const int* in_sizes, int n_in,
                              void* d_out, int out_size)
{
    const float* x  = (const float*)d_in[0];
    const int*   m  = (const int*)d_in[1];
    const float* Wq = (const float*)d_in[2];
    const float* bq = (const float*)d_in[3];
    const float* Wk = (const float*)d_in[4];
    const float* bk = (const float*)d_in[5];
    const float* Wv = (const float*)d_in[6];
    const float* bv = (const float*)d_in[7];
    const float* Wp = (const float*)d_in[8];
    const float* bp = (const float*)d_in[9];
    float* out = (float*)d_out;

    bf16 *xh, *xl, *wHi, *wLo, *qh, *ql, *kh, *kl, *vh, *vl, *yh, *yl;
    cudaGetSymbolAddress((void**)&xh, g_Xh);
    cudaGetSymbolAddress((void**)&xl, g_Xl);
    cudaGetSymbolAddress((void**)&wHi, g_Whi);
    cudaGetSymbolAddress((void**)&wLo, g_Wlo);
    cudaGetSymbolAddress((void**)&qh, g_Qh);
    cudaGetSymbolAddress((void**)&ql, g_Ql);
    cudaGetSymbolAddress((void**)&kh, g_Kh);
    cudaGetSymbolAddress((void**)&kl, g_Kl);
    cudaGetSymbolAddress((void**)&vh, g_Vh);
    cudaGetSymbolAddress((void**)&vl, g_Vl);
    cudaGetSymbolAddress((void**)&yh, g_Yh);
    cudaGetSymbolAddress((void**)&yl, g_Yl);

    static bool attr_set = false;
    if (!attr_set) {
        cudaFuncSetAttribute(gemm_mma,
                             cudaFuncAttributeMaxDynamicSharedMemorySize, GEMM_SMEM);
        cudaFuncSetAttribute(attn_mma,
                             cudaFuncAttributeMaxDynamicSharedMemorySize, ATTN_SMEM);
        attr_set = true;
    }

    conv_split<<<NELT / 4 / 256, 256>>>(x, xh, xl, NELT);
    conv_split<<<WELT / 4 / 256, 256>>>(Wq, wHi + 0 * WELT, wLo + 0 * WELT, WELT);
    conv_split<<<WELT / 4 / 256, 256>>>(Wk, wHi + 1 * WELT, wLo + 1 * WELT, WELT);
    conv_split<<<WELT / 4 / 256, 256>>>(Wv, wHi + 2 * WELT, wLo + 2 * WELT, WELT);
    conv_split<<<WELT / 4 / 256, 256>>>(Wp, wHi + 3 * WELT, wLo + 3 * WELT, WELT);

    dim3 ggrid(DD / 128, NTOK / 128);  // (8, 32)
    gemm_mma<<<ggrid, 256, GEMM_SMEM>>>(xh, xl, wHi + 0 * WELT, wLo + 0 * WELT,
                                        bq, nullptr, qh, ql, NTOK, DD, DD);
    gemm_mma<<<ggrid, 256, GEMM_SMEM>>>(xh, xl, wHi + 1 * WELT, wLo + 1 * WELT,
                                        bk, nullptr, kh, kl, NTOK, DD, DD);
    gemm_mma<<<ggrid, 256, GEMM_SMEM>>>(xh, xl, wHi + 2 * WELT, wLo + 2 * WELT,
                                        bv, nullptr, vh, vl, NTOK, DD, DD);

    dim3 agrid(LL / 128, BB * HH);     // (16, 32)
    attn_mma<<<agrid, 256, ATTN_SMEM>>>(qh, ql, kh, kl, vh, vl, m, yh, yl);

    gemm_mma<<<ggrid, 256, GEMM_SMEM>>>(yh, yl, wHi + 3 * WELT, wLo + 3 * WELT,
                                        bp, out, nullptr, nullptr, NTOK, DD, DD);
}

// round 7
// speedup vs baseline: 3.2375x; 1.0952x over previous
#include <cuda_runtime.h>
#include <cuda_bf16.h>
#include <cstdint>
#include <math.h>

#define BB 2
#define LL 2048
#define DD 1024
#define HH 16
#define DH 64
#define NEGV -10000.0f

#define NTOK (BB * LL)          // 4096
#define NELT (BB * LL * DD)     // 4194304
#define WELT (DD * DD)          // 1048576

typedef __nv_bfloat16 bf16;
typedef __nv_bfloat162 bf162;

// ---------------------------------------------------------------------------
// Scratch (__device__ globals per allocation rules) — all bf16 hi/lo pairs
// ---------------------------------------------------------------------------
__device__ bf16 g_Xh[NELT];
__device__ bf16 g_Xl[NELT];
__device__ bf16 g_Whi[4 * WELT];
__device__ bf16 g_Wlo[4 * WELT];
__device__ bf16 g_Qh[NELT];
__device__ bf16 g_Ql[NELT];
__device__ bf16 g_Kh[NELT];
__device__ bf16 g_Kl[NELT];
__device__ bf16 g_Vh[NELT];
__device__ bf16 g_Vl[NELT];
__device__ bf16 g_Yh[NELT];
__device__ bf16 g_Yl[NELT];

// ---------------------------------------------------------------------------
// PTX helpers (non-'a' features: ldmatrix sm_75+, mma.sync bf16 sm_80+,
// cp.async sm_80+)
// ---------------------------------------------------------------------------
__device__ __forceinline__ uint32_t smem_u32(const void* p) {
    uint32_t a;
    asm("{ .reg .u64 t; cvta.to.shared.u64 t, %1; cvt.u32.u64 %0, t; }"
        : "=r"(a) : "l"(p));
    return a;
}

#define LDM4(r0, r1, r2, r3, addr) \
    asm volatile("ldmatrix.sync.aligned.m8n8.x4.shared.b16 {%0,%1,%2,%3}, [%4];" \
                 : "=r"(r0), "=r"(r1), "=r"(r2), "=r"(r3) : "r"(addr))

#define LDMT4(r0, r1, r2, r3, addr) \
    asm volatile("ldmatrix.sync.aligned.m8n8.x4.trans.shared.b16 {%0,%1,%2,%3}, [%4];" \
                 : "=r"(r0), "=r"(r1), "=r"(r2), "=r"(r3) : "r"(addr))

#define MMA16816(acc, a, b0, b1) \
    asm volatile("mma.sync.aligned.m16n8k16.row.col.f32.bf16.bf16.f32 " \
                 "{%0,%1,%2,%3}, {%4,%5,%6,%7}, {%8,%9}, {%0,%1,%2,%3};" \
                 : "+f"((acc)[0]), "+f"((acc)[1]), "+f"((acc)[2]), "+f"((acc)[3]) \
                 : "r"((a)[0]), "r"((a)[1]), "r"((a)[2]), "r"((a)[3]), \
                   "r"(b0), "r"(b1))

#define CP16(dst, src) \
    asm volatile("cp.async.cg.shared.global [%0], [%1], 16;" \
                 :: "r"(dst), "l"(src) : "memory")
#define CP_COMMIT() asm volatile("cp.async.commit_group;" ::: "memory")
#define CP_WAIT0()  asm volatile("cp.async.wait_group 0;" ::: "memory")

// split a,b into packed bf16 hi pair + residual lo pair
__device__ __forceinline__ void split2(float a, float b, uint32_t& hi, uint32_t& lo) {
    bf162 h = __floats2bfloat162_rn(a, b);
    float ra = a - __bfloat162float(h.x);
    float rb = b - __bfloat162float(h.y);
    bf162 l = __floats2bfloat162_rn(ra, rb);
    hi = *(uint32_t*)&h;
    lo = *(uint32_t*)&l;
}

// ---------------------------------------------------------------------------
// fp32 -> bf16 hi/lo split
// ---------------------------------------------------------------------------
__global__ __launch_bounds__(256) void conv_split(
    const float* __restrict__ src, bf16* __restrict__ hi,
    bf16* __restrict__ lo, int n)
{
    int idx = (blockIdx.x * 256 + threadIdx.x) * 4;
    if (idx >= n) return;
    float4 v = *(const float4*)&src[idx];
    bf16 h[4], l[4];
    float f[4] = {v.x, v.y, v.z, v.w};
#pragma unroll
    for (int u = 0; u < 4; u++) {
        h[u] = __float2bfloat16(f[u]);
        l[u] = __float2bfloat16(f[u] - __bfloat162float(h[u]));
    }
    *(uint2*)&hi[idx] = *(uint2*)h;
    *(uint2*)&lo[idx] = *(uint2*)l;
}

// ---------------------------------------------------------------------------
// mma.sync bf16 GEMM, cp.async 2-stage pipelined.
// C[M,N] = A[M,K] @ W[N,K]^T + bias (hi/lo 3-term).
// Tile 128x128, BK=64, 8 warps (4Mx2N), warp tile 32x64. Pitch 72 bf16.
// ---------------------------------------------------------------------------
#define GPITCH 72
#define GT_B   (128 * GPITCH * 2)        // tile bytes: 18432
#define GSTAGE (4 * GT_B)                // 73728 per stage
#define GEMM_SMEM (2 * GSTAGE)           // 147456

__global__ __launch_bounds__(256) void gemm_mma(
    const bf16* __restrict__ Ahi, const bf16* __restrict__ Alo,
    const bf16* __restrict__ Bhi, const bf16* __restrict__ Blo,
    const float* __restrict__ bias, float* __restrict__ C,
    bf16* __restrict__ Chi, bf16* __restrict__ Clo,
    int M, int N, int K)
{
    extern __shared__ char sraw[];

    const int tid  = threadIdx.x;
    const int lane = tid & 31;
    const int wid  = tid >> 5;
    const int wm   = (wid >> 1) * 32;
    const int wn   = (wid & 1) * 64;
    const int rowBase = blockIdx.y * 128;
    const int colBase = blockIdx.x * 128;

    const uint32_t sbase = smem_u32(sraw);

    const uint32_t aOff = ((uint32_t)(wm + (lane & 15)) * GPITCH + ((lane >> 4) << 3)) * 2;
    const uint32_t bOff = ((uint32_t)(wn + (lane & 7) + ((lane >> 4) << 3)) * GPITCH
                          + (((lane >> 3) & 1) << 3)) * 2;

    const bf16* srcs[4] = {Ahi, Alo, Bhi, Blo};
    const int rbs[4] = {rowBase, rowBase, colBase, colBase};
    // per-thread load coords (4 cp.async per tile)
    const int lr = tid >> 3;             // 0..31  base row step of 32? no: idx mapping below

    float acc[2][8][4];
#pragma unroll
    for (int i = 0; i < 2; i++)
#pragma unroll
        for (int j = 0; j < 8; j++)
#pragma unroll
            for (int v = 0; v < 4; v++) acc[i][j][v] = 0.0f;

    const int nc = K >> 6;               // 64-wide chunks

    // ---- async chunk loader ----
    auto load_chunk = [&](int kc, int stage) {
        const uint32_t sb = sbase + stage * GSTAGE;
#pragma unroll
        for (int t = 0; t < 4; t++) {
            const bf16* s = srcs[t];
            const int rb = rbs[t];
            const uint32_t tb = sb + t * GT_B;
#pragma unroll
            for (int i = 0; i < 4; i++) {
                int idx = tid + i * 256;     // 0..1023
                int r = idx >> 3;            // 0..127
                int c = idx & 7;             // 16B chunk
                const bf16* gsrc = s + (size_t)(rb + r) * K + kc * 64 + c * 8;
                CP16(tb + (r * GPITCH + c * 8) * 2, gsrc);
            }
        }
        CP_COMMIT();
    };

    load_chunk(0, 0);

    for (int kc = 0; kc < nc; kc++) {
        const int cur = kc & 1;
        CP_WAIT0();
        __syncthreads();
        if (kc + 1 < nc) load_chunk(kc + 1, cur ^ 1);

        const uint32_t sb  = sbase + cur * GSTAGE;
        const uint32_t sAh = sb;
        const uint32_t sAl = sb + GT_B;
        const uint32_t sBh = sb + 2 * GT_B;
        const uint32_t sBl = sb + 3 * GT_B;

#pragma unroll
        for (int kk = 0; kk < 4; kk++) {
            const uint32_t kByte = kk * 32;
            uint32_t ah[2][4], al[2][4];
#pragma unroll
            for (int mi = 0; mi < 2; mi++) {
                uint32_t ao = aOff + mi * 16 * GPITCH * 2 + kByte;
                LDM4(ah[mi][0], ah[mi][1], ah[mi][2], ah[mi][3], sAh + ao);
                LDM4(al[mi][0], al[mi][1], al[mi][2], al[mi][3], sAl + ao);
            }
#pragma unroll
            for (int nb2 = 0; nb2 < 4; nb2++) {
                uint32_t bo = bOff + nb2 * 16 * GPITCH * 2 + kByte;
                uint32_t bh[4], bl[4];
                LDM4(bh[0], bh[1], bh[2], bh[3], sBh + bo);
                LDM4(bl[0], bl[1], bl[2], bl[3], sBl + bo);
#pragma unroll
                for (int mi = 0; mi < 2; mi++) {
                    MMA16816(acc[mi][nb2 * 2 + 0], ah[mi], bh[0], bh[1]);
                    MMA16816(acc[mi][nb2 * 2 + 1], ah[mi], bh[2], bh[3]);
                    MMA16816(acc[mi][nb2 * 2 + 0], ah[mi], bl[0], bl[1]);
                    MMA16816(acc[mi][nb2 * 2 + 1], ah[mi], bl[2], bl[3]);
                    MMA16816(acc[mi][nb2 * 2 + 0], al[mi], bh[0], bh[1]);
                    MMA16816(acc[mi][nb2 * 2 + 1], al[mi], bh[2], bh[3]);
                }
            }
        }
        __syncthreads();
    }

    const int g  = lane >> 2;
    const int tc = (lane & 3) * 2;
#pragma unroll
    for (int mi = 0; mi < 2; mi++) {
#pragma unroll
        for (int nb = 0; nb < 8; nb++) {
            int col = colBase + wn + nb * 8 + tc;
            float b0 = bias[col], b1 = bias[col + 1];
            int row0 = rowBase + wm + mi * 16 + g;
            float y0 = acc[mi][nb][0] + b0, y1 = acc[mi][nb][1] + b1;
            float y2 = acc[mi][nb][2] + b0, y3 = acc[mi][nb][3] + b1;
            if (Chi) {
                uint32_t h, l;
                split2(y0, y1, h, l);
                *(uint32_t*)&Chi[(size_t)row0 * N + col] = h;
                *(uint32_t*)&Clo[(size_t)row0 * N + col] = l;
                split2(y2, y3, h, l);
                *(uint32_t*)&Chi[(size_t)(row0 + 8) * N + col] = h;
                *(uint32_t*)&Clo[(size_t)(row0 + 8) * N + col] = l;
            } else {
                float2 o0 = {y0, y1};
                *(float2*)&C[(size_t)row0 * N + col] = o0;
                float2 o1 = {y2, y3};
                *(float2*)&C[(size_t)(row0 + 8) * N + col] = o1;
            }
        }
    }
}

// ---------------------------------------------------------------------------
// mma.sync bf16 flash attention (3-term hi/lo), cp.async 2-stage KV pipeline.
// BQ=128, BK=64, 8 warps (16 q-rows each). P stays in registers.
// ---------------------------------------------------------------------------
#define AP 72                            // smem pitch (bf16 units)
#define AT_B   (64 * AP * 2)             // KV tile bytes: 9216
#define ASTAGE (4 * AT_B)                // 36864 per stage
#define AQ_B   (128 * AP * 2)            // 18432 per Q tile
#define AQH_B  0
#define AQL_B  AQ_B
#define AKV_B  (2 * AQ_B)                // stages start: 36864
#define APAD_B (AKV_B + 2 * ASTAGE)      // 110592
#define ATTN_SMEM (APAD_B + 2 * 64 * 4)  // 111104

__global__ __launch_bounds__(256) void attn_mma(
    const bf16* __restrict__ Qh, const bf16* __restrict__ Ql,
    const bf16* __restrict__ Kh, const bf16* __restrict__ Kl,
    const bf16* __restrict__ Vh, const bf16* __restrict__ Vl,
    const int* __restrict__ msk,
    bf16* __restrict__ Yh, bf16* __restrict__ Yl)
{
    extern __shared__ char sraw[];
    float* pads = (float*)(sraw + APAD_B);

    const int tid  = threadIdx.x;
    const int lane = tid & 31;
    const int wid  = tid >> 5;
    const int wm   = wid * 16;
    const int qt   = gridDim.x - 1 - blockIdx.x;   // heavy tiles first
    const int bh   = blockIdx.y;
    const int b    = bh / HH;
    const int h    = bh % HH;

    const uint32_t sbase = smem_u32(sraw);
    const uint32_t sQH = sbase + AQH_B, sQL = sbase + AQL_B;

    // ---- async KV chunk loader ----
    auto load_kv = [&](int jt, int stage) {
        const size_t krow0 = (size_t)b * LL + (size_t)jt * 64;
        const uint32_t sb = sbase + AKV_B + stage * ASTAGE;
        const bf16* srcs[4] = {Kh, Kl, Vh, Vl};
#pragma unroll
        for (int t = 0; t < 4; t++) {
            const bf16* s = srcs[t];
            const uint32_t tb = sb + t * AT_B;
#pragma unroll
            for (int i = 0; i < 2; i++) {
                int idx = tid + i * 256;      // 0..511
                int r = idx >> 3;             // 0..63
                int c = idx & 7;
                const bf16* gsrc = s + (krow0 + r) * DD + h * DH + c * 8;
                CP16(tb + (r * AP + c * 8) * 2, gsrc);
            }
        }
        CP_COMMIT();
    };

    // ---- load Q tile (128 x 64) hi/lo via cp.async too ----
    const size_t qrow0 = (size_t)b * LL + (size_t)qt * 128;
#pragma unroll
    for (int i = 0; i < 4; i++) {
        int idx = tid + i * 256;
        int r = idx >> 3;
        int c = idx & 7;
        size_t gsrc = (qrow0 + r) * DD + h * DH + c * 8;
        CP16(sQH + (r * AP + c * 8) * 2, Qh + gsrc);
        CP16(sQL + (r * AP + c * 8) * 2, Ql + gsrc);
    }
    CP_COMMIT();
    load_kv(0, 0);

    // ldmatrix lane offsets (bytes)
    const uint32_t aOff = ((uint32_t)(wm + (lane & 15)) * AP + ((lane >> 4) << 3)) * 2;
    const uint32_t bOff = ((uint32_t)((lane & 7) + ((lane >> 4) << 3)) * AP
                          + (((lane >> 3) & 1) << 3)) * 2;
    const uint32_t vOff = ((uint32_t)(((lane >> 3) & 1) * 8 + (lane & 7)) * AP
                          + ((lane >> 4) << 3)) * 2;

    const int g   = lane >> 2;
    const int tc2 = (lane & 3) * 2;
    const int qg0 = qt * 128 + wm + g;
    const int qg1 = qg0 + 8;

    float m0 = -1e30f, m1 = -1e30f, l0 = 0.0f, l1 = 0.0f;
    float oacc[8][4];
#pragma unroll
    for (int i = 0; i < 8; i++)
#pragma unroll
        for (int v = 0; v < 4; v++) oacc[i][v] = 0.0f;

    const float scale = 0.125f;
    const int jtMax = 2 * qt + 1;

    for (int jt = 0; jt <= jtMax; jt++) {
        const int cur = jt & 1;
        // pads for this chunk (double-buffered; safe pre-sync: buffer last read
        // two iterations ago, separated by the jt-1 barrier)
        if (tid < 64)
            pads[cur * 64 + tid] =
                (1.0f - (float)msk[b * LL + jt * 64 + tid]) * NEGV;

        CP_WAIT0();
        __syncthreads();
        if (jt + 1 <= jtMax) load_kv(jt + 1, cur ^ 1);

        const uint32_t sb  = sbase + AKV_B + cur * ASTAGE;
        const uint32_t sKH = sb;
        const uint32_t sKL = sb + AT_B;
        const uint32_t sVH = sb + 2 * AT_B;
        const uint32_t sVL = sb + 3 * AT_B;
        const float* padc = pads + cur * 64;

        // ---- S = Q @ K^T (3-term) ----
        float sacc[8][4];
#pragma unroll
        for (int i = 0; i < 8; i++)
#pragma unroll
            for (int v = 0; v < 4; v++) sacc[i][v] = 0.0f;

#pragma unroll
        for (int kk = 0; kk < 4; kk++) {
            const uint32_t kByte = kk * 32;
            uint32_t ah[4], al[4];
            LDM4(ah[0], ah[1], ah[2], ah[3], sQH + aOff + kByte);
            LDM4(al[0], al[1], al[2], al[3], sQL + aOff + kByte);
#pragma unroll
            for (int nb2 = 0; nb2 < 4; nb2++) {
                uint32_t bo = bOff + nb2 * 16 * AP * 2 + kByte;
                uint32_t kh[4], kl[4];
                LDM4(kh[0], kh[1], kh[2], kh[3], sKH + bo);
                LDM4(kl[0], kl[1], kl[2], kl[3], sKL + bo);
                MMA16816(sacc[nb2 * 2 + 0], ah, kh[0], kh[1]);
                MMA16816(sacc[nb2 * 2 + 1], ah, kh[2], kh[3]);
                MMA16816(sacc[nb2 * 2 + 0], ah, kl[0], kl[1]);
                MMA16816(sacc[nb2 * 2 + 1], ah, kl[2], kl[3]);
                MMA16816(sacc[nb2 * 2 + 0], al, kh[0], kh[1]);
                MMA16816(sacc[nb2 * 2 + 1], al, kh[2], kh[3]);
            }
        }

        // ---- scale + causal + pad mask (reference order) ----
#pragma unroll
        for (int nb = 0; nb < 8; nb++) {
            int kgA = jt * 64 + nb * 8 + tc2;
            float p0 = padc[nb * 8 + tc2];
            float p1 = padc[nb * 8 + tc2 + 1];
            float v0 = sacc[nb][0] * scale; if (kgA     > qg0) v0 = NEGV; v0 += p0;
            float v1 = sacc[nb][1] * scale; if (kgA + 1 > qg0) v1 = NEGV; v1 += p1;
            float v2 = sacc[nb][2] * scale; if (kgA     > qg1) v2 = NEGV; v2 += p0;
            float v3 = sacc[nb][3] * scale; if (kgA + 1 > qg1) v3 = NEGV; v3 += p1;
            sacc[nb][0] = v0; sacc[nb][1] = v1; sacc[nb][2] = v2; sacc[nb][3] = v3;
        }

        // ---- online softmax ----
        float rmax0 = -1e30f, rmax1 = -1e30f;
#pragma unroll
        for (int nb = 0; nb < 8; nb++) {
            rmax0 = fmaxf(rmax0, fmaxf(sacc[nb][0], sacc[nb][1]));
            rmax1 = fmaxf(rmax1, fmaxf(sacc[nb][2], sacc[nb][3]));
        }
#pragma unroll
        for (int o = 1; o <= 2; o <<= 1) {
            rmax0 = fmaxf(rmax0, __shfl_xor_sync(0xffffffffu, rmax0, o));
            rmax1 = fmaxf(rmax1, __shfl_xor_sync(0xffffffffu, rmax1, o));
        }
        float m0n = fmaxf(m0, rmax0), m1n = fmaxf(m1, rmax1);
        float a0 = __expf(m0 - m0n), a1 = __expf(m1 - m1n);
        float sum0 = 0.0f, sum1 = 0.0f;
#pragma unroll
        for (int nb = 0; nb < 8; nb++) {
            sacc[nb][0] = __expf(sacc[nb][0] - m0n);
            sacc[nb][1] = __expf(sacc[nb][1] - m0n);
            sacc[nb][2] = __expf(sacc[nb][2] - m1n);
            sacc[nb][3] = __expf(sacc[nb][3] - m1n);
            sum0 += sacc[nb][0] + sacc[nb][1];
            sum1 += sacc[nb][2] + sacc[nb][3];
        }
#pragma unroll
        for (int o = 1; o <= 2; o <<= 1) {
            sum0 += __shfl_xor_sync(0xffffffffu, sum0, o);
            sum1 += __shfl_xor_sync(0xffffffffu, sum1, o);
        }
        l0 = l0 * a0 + sum0; m0 = m0n;
        l1 = l1 * a1 + sum1; m1 = m1n;
#pragma unroll
        for (int nb = 0; nb < 8; nb++) {
            oacc[nb][0] *= a0; oacc[nb][1] *= a0;
            oacc[nb][2] *= a1; oacc[nb][3] *= a1;
        }

        // ---- O += P @ V (3-term, P from registers) ----
#pragma unroll
        for (int kb = 0; kb < 4; kb++) {
            uint32_t pah[4], pal[4];
            split2(sacc[2 * kb][0],     sacc[2 * kb][1],     pah[0], pal[0]);
            split2(sacc[2 * kb][2],     sacc[2 * kb][3],     pah[1], pal[1]);
            split2(sacc[2 * kb + 1][0], sacc[2 * kb + 1][1], pah[2], pal[2]);
            split2(sacc[2 * kb + 1][2], sacc[2 * kb + 1][3], pah[3], pal[3]);
#pragma unroll
            for (int nb2 = 0; nb2 < 4; nb2++) {
                uint32_t vo = vOff + (kb * 16 * AP + nb2 * 16) * 2;
                uint32_t vh[4], vl[4];
                LDMT4(vh[0], vh[1], vh[2], vh[3], sVH + vo);
                LDMT4(vl[0], vl[1], vl[2], vl[3], sVL + vo);
                MMA16816(oacc[nb2 * 2 + 0], pah, vh[0], vh[1]);
                MMA16816(oacc[nb2 * 2 + 1], pah, vh[2], vh[3]);
                MMA16816(oacc[nb2 * 2 + 0], pah, vl[0], vl[1]);
                MMA16816(oacc[nb2 * 2 + 1], pah, vl[2], vl[3]);
                MMA16816(oacc[nb2 * 2 + 0], pal, vh[0], vh[1]);
                MMA16816(oacc[nb2 * 2 + 1], pal, vh[2], vh[3]);
            }
        }
    }

    // ---- finalize + write Y hi/lo ----
    float inv0 = 1.0f / l0, inv1 = 1.0f / l1;
    const size_t row0 = qrow0 + wm + g;
#pragma unroll
    for (int nb = 0; nb < 8; nb++) {
        int col = h * DH + nb * 8 + tc2;
        uint32_t hzz, lzz;
        split2(oacc[nb][0] * inv0, oacc[nb][1] * inv0, hzz, lzz);
        *(uint32_t*)&Yh[row0 * DD + col] = hzz;
        *(uint32_t*)&Yl[row0 * DD + col] = lzz;
        split2(oacc[nb][2] * inv1, oacc[nb][3] * inv1, hzz, lzz);
        *(uint32_t*)&Yh[(row0 + 8) * DD + col] = hzz;
        *(uint32_t*)&Yl[(row0 + 8) * DD + col] = lzz;
    }
}

// ---------------------------------------------------------------------------
extern "C" void kernel_launch(void* const* d_in, const int* in_sizes, int n_in,
                              void* d_out, int out_size)
{
    const float* x  = (const float*)d_in[0];
    const int*   m  = (const int*)d_in[1];
    const float* Wq = (const float*)d_in[2];
    const float* bq = (const float*)d_in[3];
    const float* Wk = (const float*)d_in[4];
    const float* bk = (const float*)d_in[5];
    const float* Wv = (const float*)d_in[6];
    const float* bv = (const float*)d_in[7];
    const float* Wp = (const float*)d_in[8];
    const float* bp = (const float*)d_in[9];
    float* out = (float*)d_out;

    bf16 *xh, *xl, *wHi, *wLo, *qh, *ql, *kh, *kl, *vh, *vl, *yh, *yl;
    cudaGetSymbolAddress((void**)&xh, g_Xh);
    cudaGetSymbolAddress((void**)&xl, g_Xl);
    cudaGetSymbolAddress((void**)&wHi, g_Whi);
    cudaGetSymbolAddress((void**)&wLo, g_Wlo);
    cudaGetSymbolAddress((void**)&qh, g_Qh);
    cudaGetSymbolAddress((void**)&ql, g_Ql);
    cudaGetSymbolAddress((void**)&kh, g_Kh);
    cudaGetSymbolAddress((void**)&kl, g_Kl);
    cudaGetSymbolAddress((void**)&vh, g_Vh);
    cudaGetSymbolAddress((void**)&vl, g_Vl);
    cudaGetSymbolAddress((void**)&yh, g_Yh);
    cudaGetSymbolAddress((void**)&yl, g_Yl);

    static bool attr_set = false;
    if (!attr_set) {
        cudaFuncSetAttribute(gemm_mma,
                             cudaFuncAttributeMaxDynamicSharedMemorySize, GEMM_SMEM);
        cudaFuncSetAttribute(attn_mma,
                             cudaFuncAttributeMaxDynamicSharedMemorySize, ATTN_SMEM);
        attr_set = true;
    }

    conv_split<<<NELT / 4 / 256, 256>>>(x, xh, xl, NELT);
    conv_split<<<WELT / 4 / 256, 256>>>(Wq, wHi + 0 * WELT, wLo + 0 * WELT, WELT);
    conv_split<<<WELT / 4 / 256, 256>>>(Wk, wHi + 1 * WELT, wLo + 1 * WELT, WELT);
    conv_split<<<WELT / 4 / 256, 256>>>(Wv, wHi + 2 * WELT, wLo + 2 * WELT, WELT);
    conv_split<<<WELT / 4 / 256, 256>>>(Wp, wHi + 3 * WELT, wLo + 3 * WELT, WELT);

    dim3 ggrid(DD / 128, NTOK / 128);  // (8, 32)
    gemm_mma<<<ggrid, 256, GEMM_SMEM>>>(xh, xl, wHi + 0 * WELT, wLo + 0 * WELT,
                                        bq, nullptr, qh, ql, NTOK, DD, DD);
    gemm_mma<<<ggrid, 256, GEMM_SMEM>>>(xh, xl, wHi + 1 * WELT, wLo + 1 * WELT,
                                        bk, nullptr, kh, kl, NTOK, DD, DD);
    gemm_mma<<<ggrid, 256, GEMM_SMEM>>>(xh, xl, wHi + 2 * WELT, wLo + 2 * WELT,
                                        bv, nullptr, vh, vl, NTOK, DD, DD);

    dim3 agrid(LL / 128, BB * HH);     // (16, 32)
    attn_mma<<<agrid, 256, ATTN_SMEM>>>(qh, ql, kh, kl, vh, vl, m, yh, yl);

    gemm_mma<<<ggrid, 256, GEMM_SMEM>>>(yh, yl, wHi + 3 * WELT, wLo + 3 * WELT,
                                        bp, out, nullptr, nullptr, NTOK, DD, DD);
}

// round 8
// speedup vs baseline: 4.4145x; 1.3635x over previous
#include <cuda_runtime.h>
#include <cuda_fp16.h>
#include <cstdint>
#include <math.h>

#define BB 2
#define LL 2048
#define DD 1024
#define HH 16
#define DH 64
#define NEGV -10000.0f

#define NTOK (BB * LL)          // 4096
#define NELT (BB * LL * DD)     // 4194304
#define WELT (DD * DD)          // 1048576

// ---------------------------------------------------------------------------
// Scratch (__device__ globals per allocation rules)
// ---------------------------------------------------------------------------
__device__ __half g_Xh[NELT];
__device__ __half g_Xl[NELT];
__device__ __half g_Wh[4 * WELT];   // Wq,Wk,Wv,Wp single fp16
__device__ __half g_Qh[NELT];
__device__ __half g_Ql[NELT];
__device__ __half g_Kh[NELT];       // K single fp16
__device__ __half g_Vh[NELT];       // V single fp16
__device__ __half g_Yh[NELT];
__device__ __half g_Yl[NELT];

// ---------------------------------------------------------------------------
// PTX helpers (non-'a' features: ldmatrix, mma.sync f16, cp.async)
// ---------------------------------------------------------------------------
__device__ __forceinline__ uint32_t smem_u32(const void* p) {
    uint32_t a;
    asm("{ .reg .u64 t; cvta.to.shared.u64 t, %1; cvt.u32.u64 %0, t; }"
        : "=r"(a) : "l"(p));
    return a;
}

#define LDM4(r0, r1, r2, r3, addr) \
    asm volatile("ldmatrix.sync.aligned.m8n8.x4.shared.b16 {%0,%1,%2,%3}, [%4];" \
                 : "=r"(r0), "=r"(r1), "=r"(r2), "=r"(r3) : "r"(addr))

#define LDMT4(r0, r1, r2, r3, addr) \
    asm volatile("ldmatrix.sync.aligned.m8n8.x4.trans.shared.b16 {%0,%1,%2,%3}, [%4];" \
                 : "=r"(r0), "=r"(r1), "=r"(r2), "=r"(r3) : "r"(addr))

#define MMA16816(acc, a, b0, b1) \
    asm volatile("mma.sync.aligned.m16n8k16.row.col.f32.f16.f16.f32 " \
                 "{%0,%1,%2,%3}, {%4,%5,%6,%7}, {%8,%9}, {%0,%1,%2,%3};" \
                 : "+f"((acc)[0]), "+f"((acc)[1]), "+f"((acc)[2]), "+f"((acc)[3]) \
                 : "r"((a)[0]), "r"((a)[1]), "r"((a)[2]), "r"((a)[3]), \
                   "r"(b0), "r"(b1))

#define CP16(dst, src) \
    asm volatile("cp.async.cg.shared.global [%0], [%1], 16;" \
                 :: "r"(dst), "l"(src) : "memory")
#define CP_COMMIT() asm volatile("cp.async.commit_group;" ::: "memory")
#define CP_WAIT1()  asm volatile("cp.async.wait_group 1;" ::: "memory")

// split a,b into packed fp16 hi pair + residual lo pair
__device__ __forceinline__ void split2h(float a, float b, uint32_t& hi, uint32_t& lo) {
    __half2 h = __floats2half2_rn(a, b);
    __half2 l = __floats2half2_rn(a - __half2float(h.x), b - __half2float(h.y));
    hi = *(uint32_t*)&h;
    lo = *(uint32_t*)&l;
}

// ---------------------------------------------------------------------------
// conversions
// ---------------------------------------------------------------------------
__global__ __launch_bounds__(256) void conv_dual(
    const float* __restrict__ src, __half* __restrict__ hi,
    __half* __restrict__ lo, int n)
{
    int idx = (blockIdx.x * 256 + threadIdx.x) * 4;
    if (idx >= n) return;
    float4 v = *(const float4*)&src[idx];
    float f[4] = {v.x, v.y, v.z, v.w};
    __half h[4], l[4];
#pragma unroll
    for (int u = 0; u < 4; u++) {
        h[u] = __float2half_rn(f[u]);
        l[u] = __float2half_rn(f[u] - __half2float(h[u]));
    }
    *(uint2*)&hi[idx] = *(uint2*)h;
    *(uint2*)&lo[idx] = *(uint2*)l;
}

__global__ __launch_bounds__(256) void conv_one(
    const float* __restrict__ src, __half* __restrict__ dst, int n)
{
    int idx = (blockIdx.x * 256 + threadIdx.x) * 4;
    if (idx >= n) return;
    float4 v = *(const float4*)&src[idx];
    __half h[4] = {__float2half_rn(v.x), __float2half_rn(v.y),
                   __float2half_rn(v.z), __float2half_rn(v.w)};
    *(uint2*)&dst[idx] = *(uint2*)h;
}

// ---------------------------------------------------------------------------
// fp16 2-term GEMM: C = (Ah + Al) @ W^T + bias. W single fp16.
// Tile 128x128, BK=64, 8 warps (4Mx2N), warp tile 32x64. Pitch 72.
// 3-stage cp.async pipeline, one barrier per chunk. Fused QKV via blockIdx.z.
// ---------------------------------------------------------------------------
#define GPITCH 72
#define GT_B   (128 * GPITCH * 2)        // 18432
#define GSTAGE (3 * GT_B)                // 55296 (Ah, Al, W)
#define GEMM_SMEM (3 * GSTAGE)           // 165888

struct GArgs {
    const __half* W[3];
    const float*  bias[3];
    __half* oh[3];
    __half* ol[3];
};

__global__ __launch_bounds__(256) void gemm_mma(
    const __half* __restrict__ Ah, const __half* __restrict__ Al,
    GArgs args, float* __restrict__ Cf, int M, int N, int K)
{
    extern __shared__ char sraw[];

    const int z = blockIdx.z;
    const __half* W   = args.W[z];
    const float* bias = args.bias[z];
    __half* Chi = args.oh[z];
    __half* Clo = args.ol[z];

    const int tid  = threadIdx.x;
    const int lane = tid & 31;
    const int wid  = tid >> 5;
    const int wm   = (wid >> 1) * 32;
    const int wn   = (wid & 1) * 64;
    const int rowBase = blockIdx.y * 128;
    const int colBase = blockIdx.x * 128;

    const uint32_t sbase = smem_u32(sraw);

    const uint32_t aOff = ((uint32_t)(wm + (lane & 15)) * GPITCH + ((lane >> 4) << 3)) * 2;
    const uint32_t bOff = ((uint32_t)(wn + (lane & 7) + ((lane >> 4) << 3)) * GPITCH
                          + (((lane >> 3) & 1) << 3)) * 2;

    float acc[2][8][4];
#pragma unroll
    for (int i = 0; i < 2; i++)
#pragma unroll
        for (int j = 0; j < 8; j++)
#pragma unroll
            for (int v = 0; v < 4; v++) acc[i][j][v] = 0.0f;

    const int nc = K >> 6;

    auto load_chunk = [&](int kc, int stage) {
        const uint32_t sb = sbase + stage * GSTAGE;
        const __half* srcs[3] = {Ah, Al, W};
        const int rbs[3] = {rowBase, rowBase, colBase};
#pragma unroll
        for (int t = 0; t < 3; t++) {
            const __half* s = srcs[t];
            const int rb = rbs[t];
            const uint32_t tb = sb + t * GT_B;
#pragma unroll
            for (int i = 0; i < 4; i++) {
                int idx = tid + i * 256;
                int r = idx >> 3;
                int c = idx & 7;
                CP16(tb + (r * GPITCH + c * 8) * 2,
                     s + (size_t)(rb + r) * K + kc * 64 + c * 8);
            }
        }
        CP_COMMIT();
    };

    load_chunk(0, 0);
    load_chunk(1, 1);

    for (int kc = 0; kc < nc; kc++) {
        CP_WAIT1();                       // stage kc arrived
        __syncthreads();                  // also guards buffer reuse
        if (kc + 2 < nc) load_chunk(kc + 2, (kc + 2) % 3);

        const uint32_t sb  = sbase + (kc % 3) * GSTAGE;
        const uint32_t sAh = sb;
        const uint32_t sAl = sb + GT_B;
        const uint32_t sW  = sb + 2 * GT_B;

#pragma unroll
        for (int kk = 0; kk < 4; kk++) {
            const uint32_t kByte = kk * 32;
            uint32_t ah[2][4], al[2][4];
#pragma unroll
            for (int mi = 0; mi < 2; mi++) {
                uint32_t ao = aOff + mi * 16 * GPITCH * 2 + kByte;
                LDM4(ah[mi][0], ah[mi][1], ah[mi][2], ah[mi][3], sAh + ao);
                LDM4(al[mi][0], al[mi][1], al[mi][2], al[mi][3], sAl + ao);
            }
#pragma unroll
            for (int nb2 = 0; nb2 < 4; nb2++) {
                uint32_t bo = bOff + nb2 * 16 * GPITCH * 2 + kByte;
                uint32_t bh[4];
                LDM4(bh[0], bh[1], bh[2], bh[3], sW + bo);
#pragma unroll
                for (int mi = 0; mi < 2; mi++) {
                    MMA16816(acc[mi][nb2 * 2 + 0], ah[mi], bh[0], bh[1]);
                    MMA16816(acc[mi][nb2 * 2 + 1], ah[mi], bh[2], bh[3]);
                    MMA16816(acc[mi][nb2 * 2 + 0], al[mi], bh[0], bh[1]);
                    MMA16816(acc[mi][nb2 * 2 + 1], al[mi], bh[2], bh[3]);
                }
            }
        }
    }

    const int g  = lane >> 2;
    const int tc = (lane & 3) * 2;
#pragma unroll
    for (int mi = 0; mi < 2; mi++) {
#pragma unroll
        for (int nb = 0; nb < 8; nb++) {
            int col = colBase + wn + nb * 8 + tc;
            float b0 = bias[col], b1 = bias[col + 1];
            int row0 = rowBase + wm + mi * 16 + g;
            float y0 = acc[mi][nb][0] + b0, y1 = acc[mi][nb][1] + b1;
            float y2 = acc[mi][nb][2] + b0, y3 = acc[mi][nb][3] + b1;
            if (Cf) {
                float2 o0 = {y0, y1};
                *(float2*)&Cf[(size_t)row0 * N + col] = o0;
                float2 o1 = {y2, y3};
                *(float2*)&Cf[(size_t)(row0 + 8) * N + col] = o1;
            } else if (Clo) {
                uint32_t h, l;
                split2h(y0, y1, h, l);
                *(uint32_t*)&Chi[(size_t)row0 * N + col] = h;
                *(uint32_t*)&Clo[(size_t)row0 * N + col] = l;
                split2h(y2, y3, h, l);
                *(uint32_t*)&Chi[(size_t)(row0 + 8) * N + col] = h;
                *(uint32_t*)&Clo[(size_t)(row0 + 8) * N + col] = l;
            } else {
                __half2 h0 = __floats2half2_rn(y0, y1);
                *(uint32_t*)&Chi[(size_t)row0 * N + col] = *(uint32_t*)&h0;
                __half2 h1 = __floats2half2_rn(y2, y3);
                *(uint32_t*)&Chi[(size_t)(row0 + 8) * N + col] = *(uint32_t*)&h1;
            }
        }
    }
}

// ---------------------------------------------------------------------------
// fp16 2-term flash attention. Q dual (Qh+Ql), K/V single fp16.
// BQ=128, BK=64, 8 warps. 3-stage cp.async KV pipeline, 1 barrier/iter.
// ---------------------------------------------------------------------------
#define AP 72
#define AKV_T (64 * AP * 2)              // 9216
#define ASTG  (2 * AKV_T)                // 18432 (Kh + Vh)
#define AQ_B  (128 * AP * 2)             // 18432
#define AKV_B (2 * AQ_B)                 // 36864
#define APAD_B (AKV_B + 3 * ASTG)        // 92160
#define ATTN_SMEM (APAD_B + 3 * 64 * 4)  // 92928

__global__ __launch_bounds__(256) void attn_mma(
    const __half* __restrict__ Qh, const __half* __restrict__ Ql,
    const __half* __restrict__ Kh, const __half* __restrict__ Vh,
    const int* __restrict__ msk,
    __half* __restrict__ Yh, __half* __restrict__ Yl)
{
    extern __shared__ char sraw[];
    float* pads = (float*)(sraw + APAD_B);

    const int tid  = threadIdx.x;
    const int lane = tid & 31;
    const int wid  = tid >> 5;
    const int wm   = wid * 16;
    const int qt   = gridDim.x - 1 - blockIdx.x;   // heavy tiles first
    const int bh   = blockIdx.y;
    const int b    = bh / HH;
    const int h    = bh % HH;

    const uint32_t sbase = smem_u32(sraw);
    const uint32_t sQH = sbase, sQL = sbase + AQ_B;

    auto load_kv = [&](int jt, int stage) {
        const size_t krow0 = (size_t)b * LL + (size_t)jt * 64;
        const uint32_t sb = sbase + AKV_B + stage * ASTG;
#pragma unroll
        for (int i = 0; i < 2; i++) {
            int idx = tid + i * 256;      // 0..511
            int r = idx >> 3;
            int c = idx & 7;
            const size_t gsrc = (krow0 + r) * DD + h * DH + c * 8;
            uint32_t so = (r * AP + c * 8) * 2;
            CP16(sb + so,          Kh + gsrc);
            CP16(sb + AKV_T + so,  Vh + gsrc);
        }
        CP_COMMIT();
    };

    // Q tile (128 x 64) hi/lo
    const size_t qrow0 = (size_t)b * LL + (size_t)qt * 128;
#pragma unroll
    for (int i = 0; i < 4; i++) {
        int idx = tid + i * 256;
        int r = idx >> 3;
        int c = idx & 7;
        size_t gsrc = (qrow0 + r) * DD + h * DH + c * 8;
        CP16(sQH + (r * AP + c * 8) * 2, Qh + gsrc);
        CP16(sQL + (r * AP + c * 8) * 2, Ql + gsrc);
    }
    CP_COMMIT();
    const int jtMax = 2 * qt + 1;
    load_kv(0, 0);
    if (1 <= jtMax) load_kv(1, 1); else CP_COMMIT();

    const uint32_t aOff = ((uint32_t)(wm + (lane & 15)) * AP + ((lane >> 4) << 3)) * 2;
    const uint32_t bOff = ((uint32_t)((lane & 7) + ((lane >> 4) << 3)) * AP
                          + (((lane >> 3) & 1) << 3)) * 2;
    const uint32_t vOff = ((uint32_t)(((lane >> 3) & 1) * 8 + (lane & 7)) * AP
                          + ((lane >> 4) << 3)) * 2;

    const int g   = lane >> 2;
    const int tc2 = (lane & 3) * 2;
    const int qg0 = qt * 128 + wm + g;
    const int qg1 = qg0 + 8;

    float m0 = -1e30f, m1 = -1e30f, l0 = 0.0f, l1 = 0.0f;
    float oacc[8][4];
#pragma unroll
    for (int i = 0; i < 8; i++)
#pragma unroll
        for (int v = 0; v < 4; v++) oacc[i][v] = 0.0f;

    const float scale = 0.125f;

    for (int jt = 0; jt <= jtMax; jt++) {
        const int cur = jt % 3;
        if (tid < 64)
            pads[cur * 64 + tid] =
                (1.0f - (float)msk[b * LL + jt * 64 + tid]) * NEGV;

        CP_WAIT1();
        __syncthreads();
        if (jt + 2 <= jtMax) load_kv(jt + 2, (jt + 2) % 3);

        const uint32_t sb  = sbase + AKV_B + cur * ASTG;
        const uint32_t sKH = sb;
        const uint32_t sVH = sb + AKV_T;
        const float* padc = pads + cur * 64;

        // ---- S = (Qh+Ql) @ Kh^T ----
        float sacc[8][4];
#pragma unroll
        for (int i = 0; i < 8; i++)
#pragma unroll
            for (int v = 0; v < 4; v++) sacc[i][v] = 0.0f;

#pragma unroll
        for (int kk = 0; kk < 4; kk++) {
            const uint32_t kByte = kk * 32;
            uint32_t ah[4], al[4];
            LDM4(ah[0], ah[1], ah[2], ah[3], sQH + aOff + kByte);
            LDM4(al[0], al[1], al[2], al[3], sQL + aOff + kByte);
#pragma unroll
            for (int nb2 = 0; nb2 < 4; nb2++) {
                uint32_t bo = bOff + nb2 * 16 * AP * 2 + kByte;
                uint32_t kh[4];
                LDM4(kh[0], kh[1], kh[2], kh[3], sKH + bo);
                MMA16816(sacc[nb2 * 2 + 0], ah, kh[0], kh[1]);
                MMA16816(sacc[nb2 * 2 + 1], ah, kh[2], kh[3]);
                MMA16816(sacc[nb2 * 2 + 0], al, kh[0], kh[1]);
                MMA16816(sacc[nb2 * 2 + 1], al, kh[2], kh[3]);
            }
        }

        // ---- scale + causal + pad mask ----
#pragma unroll
        for (int nb = 0; nb < 8; nb++) {
            int kgA = jt * 64 + nb * 8 + tc2;
            float p0 = padc[nb * 8 + tc2];
            float p1 = padc[nb * 8 + tc2 + 1];
            float v0 = sacc[nb][0] * scale; if (kgA     > qg0) v0 = NEGV; v0 += p0;
            float v1 = sacc[nb][1] * scale; if (kgA + 1 > qg0) v1 = NEGV; v1 += p1;
            float v2 = sacc[nb][2] * scale; if (kgA     > qg1) v2 = NEGV; v2 += p0;
            float v3 = sacc[nb][3] * scale; if (kgA + 1 > qg1) v3 = NEGV; v3 += p1;
            sacc[nb][0] = v0; sacc[nb][1] = v1; sacc[nb][2] = v2; sacc[nb][3] = v3;
        }

        // ---- online softmax ----
        float rmax0 = -1e30f, rmax1 = -1e30f;
#pragma unroll
        for (int nb = 0; nb < 8; nb++) {
            rmax0 = fmaxf(rmax0, fmaxf(sacc[nb][0], sacc[nb][1]));
            rmax1 = fmaxf(rmax1, fmaxf(sacc[nb][2], sacc[nb][3]));
        }
#pragma unroll
        for (int o = 1; o <= 2; o <<= 1) {
            rmax0 = fmaxf(rmax0, __shfl_xor_sync(0xffffffffu, rmax0, o));
            rmax1 = fmaxf(rmax1, __shfl_xor_sync(0xffffffffu, rmax1, o));
        }
        float m0n = fmaxf(m0, rmax0), m1n = fmaxf(m1, rmax1);
        float a0 = __expf(m0 - m0n), a1 = __expf(m1 - m1n);
        float sum0 = 0.0f, sum1 = 0.0f;
#pragma unroll
        for (int nb = 0; nb < 8; nb++) {
            sacc[nb][0] = __expf(sacc[nb][0] - m0n);
            sacc[nb][1] = __expf(sacc[nb][1] - m0n);
            sacc[nb][2] = __expf(sacc[nb][2] - m1n);
            sacc[nb][3] = __expf(sacc[nb][3] - m1n);
            sum0 += sacc[nb][0] + sacc[nb][1];
            sum1 += sacc[nb][2] + sacc[nb][3];
        }
#pragma unroll
        for (int o = 1; o <= 2; o <<= 1) {
            sum0 += __shfl_xor_sync(0xffffffffu, sum0, o);
            sum1 += __shfl_xor_sync(0xffffffffu, sum1, o);
        }
        l0 = l0 * a0 + sum0; m0 = m0n;
        l1 = l1 * a1 + sum1; m1 = m1n;
#pragma unroll
        for (int nb = 0; nb < 8; nb++) {
            oacc[nb][0] *= a0; oacc[nb][1] *= a0;
            oacc[nb][2] *= a1; oacc[nb][3] *= a1;
        }

        // ---- O += (Ph+Pl) @ Vh ----
#pragma unroll
        for (int kb = 0; kb < 4; kb++) {
            uint32_t ph[4], pl[4];
            split2h(sacc[2 * kb][0],     sacc[2 * kb][1],     ph[0], pl[0]);
            split2h(sacc[2 * kb][2],     sacc[2 * kb][3],     ph[1], pl[1]);
            split2h(sacc[2 * kb + 1][0], sacc[2 * kb + 1][1], ph[2], pl[2]);
            split2h(sacc[2 * kb + 1][2], sacc[2 * kb + 1][3], ph[3], pl[3]);
#pragma unroll
            for (int nb2 = 0; nb2 < 4; nb2++) {
                uint32_t vo = vOff + (kb * 16 * AP + nb2 * 16) * 2;
                uint32_t vh[4];
                LDMT4(vh[0], vh[1], vh[2], vh[3], sVH + vo);
                MMA16816(oacc[nb2 * 2 + 0], ph, vh[0], vh[1]);
                MMA16816(oacc[nb2 * 2 + 1], ph, vh[2], vh[3]);
                MMA16816(oacc[nb2 * 2 + 0], pl, vh[0], vh[1]);
                MMA16816(oacc[nb2 * 2 + 1], pl, vh[2], vh[3]);
            }
        }
    }

    // ---- finalize + write Y hi/lo ----
    float inv0 = 1.0f / l0, inv1 = 1.0f / l1;
    const size_t row0 = qrow0 + wm + g;
#pragma unroll
    for (int nb = 0; nb < 8; nb++) {
        int col = h * DH + nb * 8 + tc2;
        uint32_t hz, lz;
        split2h(oacc[nb][0] * inv0, oacc[nb][1] * inv0, hz, lz);
        *(uint32_t*)&Yh[row0 * DD + col] = hz;
        *(uint32_t*)&Yl[row0 * DD + col] = lz;
        split2h(oacc[nb][2] * inv1, oacc[nb][3] * inv1, hz, lz);
        *(uint32_t*)&Yh[(row0 + 8) * DD + col] = hz;
        *(uint32_t*)&Yl[(row0 + 8) * DD + col] = lz;
    }
}

// ---------------------------------------------------------------------------
extern "C" void kernel_launch(void* const* d_in, const int* in_sizes, int n_in,
                              void* d_out, int out_size)
{
    const float* x  = (const float*)d_in[0];
    const int*   m  = (const int*)d_in[1];
    const float* Wq = (const float*)d_in[2];
    const float* bq = (const float*)d_in[3];
    const float* Wk = (const float*)d_in[4];
    const float* bk = (const float*)d_in[5];
    const float* Wv = (const float*)d_in[6];
    const float* bv = (const float*)d_in[7];
    const float* Wp = (const float*)d_in[8];
    const float* bp = (const float*)d_in[9];
    float* out = (float*)d_out;

    __half *xh, *xl, *wh, *qh, *ql, *kh, *vh, *yh, *yl;
    cudaGetSymbolAddress((void**)&xh, g_Xh);
    cudaGetSymbolAddress((void**)&xl, g_Xl);
    cudaGetSymbolAddress((void**)&wh, g_Wh);
    cudaGetSymbolAddress((void**)&qh, g_Qh);
    cudaGetSymbolAddress((void**)&ql, g_Ql);
    cudaGetSymbolAddress((void**)&kh, g_Kh);
    cudaGetSymbolAddress((void**)&vh, g_Vh);
    cudaGetSymbolAddress((void**)&yh, g_Yh);
    cudaGetSymbolAddress((void**)&yl, g_Yl);

    static bool attr_set = false;
    if (!attr_set) {
        cudaFuncSetAttribute(gemm_mma,
                             cudaFuncAttributeMaxDynamicSharedMemorySize, GEMM_SMEM);
        cudaFuncSetAttribute(attn_mma,
                             cudaFuncAttributeMaxDynamicSharedMemorySize, ATTN_SMEM);
        attr_set = true;
    }

    conv_dual<<<NELT / 4 / 256, 256>>>(x, xh, xl, NELT);
    conv_one<<<WELT / 4 / 256, 256>>>(Wq, wh + 0 * WELT, WELT);
    conv_one<<<WELT / 4 / 256, 256>>>(Wk, wh + 1 * WELT, WELT);
    conv_one<<<WELT / 4 / 256, 256>>>(Wv, wh + 2 * WELT, WELT);
    conv_one<<<WELT / 4 / 256, 256>>>(Wp, wh + 3 * WELT, WELT);

    // Fused QKV (z = 0:Q dual out, 1:K single, 2:V single)
    GArgs qkv;
    qkv.W[0] = wh + 0 * WELT; qkv.W[1] = wh + 1 * WELT; qkv.W[2] = wh + 2 * WELT;
    qkv.bias[0] = bq; qkv.bias[1] = bk; qkv.bias[2] = bv;
    qkv.oh[0] = qh;  qkv.oh[1] = kh;  qkv.oh[2] = vh;
    qkv.ol[0] = ql;  qkv.ol[1] = nullptr; qkv.ol[2] = nullptr;
    dim3 qgrid(DD / 128, NTOK / 128, 3);   // (8, 32, 3)
    gemm_mma<<<qgrid, 256, GEMM_SMEM>>>(xh, xl, qkv, nullptr, NTOK, DD, DD);

    dim3 agrid(LL / 128, BB * HH);         // (16, 32)
    attn_mma<<<agrid, 256, ATTN_SMEM>>>(qh, ql, kh, vh, m, yh, yl);

    GArgs proj;
    proj.W[0] = wh + 3 * WELT; proj.W[1] = nullptr; proj.W[2] = nullptr;
    proj.bias[0] = bp; proj.bias[1] = nullptr; proj.bias[2] = nullptr;
    proj.oh[0] = nullptr; proj.oh[1] = nullptr; proj.oh[2] = nullptr;
    proj.ol[0] = nullptr; proj.ol[1] = nullptr; proj.ol[2] = nullptr;
    dim3 pgrid(DD / 128, NTOK / 128, 1);   // (8, 32, 1)
    gemm_mma<<<pgrid, 256, GEMM_SMEM>>>(yh, yl, proj, out, NTOK, DD, DD);
}